// round 2
// baseline (speedup 1.0000x reference)
#include <cuda_runtime.h>
#include <math.h>

// ---------------- problem dims (fixed) ----------------
#define BATCH   16
#define SEQ     576
#define T_TOK   9216            // BATCH*SEQ
#define D_IN    1024
#define D_MODEL 2048
#define NEXP    4
#define H_FF    8192
#define CAP     3456            // int(1.5*9216/4)
#define ECAP    (NEXP*CAP)      // 13824

// output layout (reference tuple flattened)
#define OUT_FINAL   0
#define OUT_COUNTS  (T_TOK*D_MODEL)            // 18874368
#define OUT_EXTRAS_N 9225                      // 4+4+1+9216

// ---------------- scratch (__device__ globals; no allocation) ----------------
__device__ float g_xn[(size_t)T_TOK * D_IN];
__device__ float g_t [(size_t)T_TOK * D_MODEL];
__device__ float g_probs[(size_t)T_TOK * NEXP];
__device__ float g_pmax [T_TOK];
__device__ int   g_routes[T_TOK];
__device__ int   g_keep  [T_TOK];
__device__ int   g_slot2tok[ECAP];
__device__ int   g_Mfill[NEXP];
__device__ float g_counts[NEXP];
__device__ float g_probsum[NEXP];
__device__ float g_ndrop[1];
__device__ float g_h[(size_t)ECAP * H_FF];     // 453 MB

__device__ __forceinline__ float gelu_exact(float x) {
    return 0.5f * x * (1.0f + erff(x * 0.70710678118654752f));
}

// ---------------- LayerNorm ----------------
__global__ void ln_kernel(const float* __restrict__ x,
                          const float* __restrict__ g,
                          const float* __restrict__ b)
{
    int tok = blockIdx.x;
    int tid = threadIdx.x;
    const float* xr = x + (size_t)tok * D_IN;
    __shared__ float red[256];

    float s = 0.f;
    for (int i = tid; i < D_IN; i += 256) s += xr[i];
    red[tid] = s; __syncthreads();
    for (int o = 128; o > 0; o >>= 1) { if (tid < o) red[tid] += red[tid + o]; __syncthreads(); }
    float mu = red[0] * (1.0f / D_IN);
    __syncthreads();

    float v = 0.f;
    for (int i = tid; i < D_IN; i += 256) { float d = xr[i] - mu; v += d * d; }
    red[tid] = v; __syncthreads();
    for (int o = 128; o > 0; o >>= 1) { if (tid < o) red[tid] += red[tid + o]; __syncthreads(); }
    float rstd = rsqrtf(red[0] * (1.0f / D_IN) + 1e-5f);

    float* xo = g_xn + (size_t)tok * D_IN;
    for (int i = tid; i < D_IN; i += 256)
        xo[i] = (xr[i] - mu) * rstd * g[i] + b[i];
}

// ---------------- pre-linear GEMM: t = gelu(xn @ pre_W + pre_b) ----------------
// M=9216, K=1024, N=2048. 128x128x8 tile, 256 threads, 8x8 per thread.
__global__ void pre_gemm(const float* __restrict__ W,
                         const float* __restrict__ bias)
{
    const int K = D_IN, N = D_MODEL;
    int m0 = blockIdx.y * 128;
    int n0 = blockIdx.x * 128;
    int tid = threadIdx.x;

    __shared__ float As[8][128];
    __shared__ float Bs[8][128];

    int aRow = tid >> 1;          // 0..127
    int aCol = (tid & 1) * 4;     // 0 or 4
    int bRow = tid >> 5;          // 0..7
    int bCol = (tid & 31) * 4;    // 0..124
    int ty = tid >> 4, tx = tid & 15;

    const float* aPtr = g_xn + (size_t)(m0 + aRow) * K + aCol;

    float acc[8][8];
#pragma unroll
    for (int i = 0; i < 8; i++)
#pragma unroll
        for (int j = 0; j < 8; j++) acc[i][j] = 0.f;

    for (int k0 = 0; k0 < K; k0 += 8) {
        float4 av = *reinterpret_cast<const float4*>(aPtr + k0);
        float4 bv = *reinterpret_cast<const float4*>(&W[(size_t)(k0 + bRow) * N + n0 + bCol]);
        As[aCol + 0][aRow] = av.x; As[aCol + 1][aRow] = av.y;
        As[aCol + 2][aRow] = av.z; As[aCol + 3][aRow] = av.w;
        *reinterpret_cast<float4*>(&Bs[bRow][bCol]) = bv;
        __syncthreads();
#pragma unroll
        for (int k = 0; k < 8; k++) {
            float ra[8], rb[8];
#pragma unroll
            for (int i = 0; i < 8; i++) ra[i] = As[k][ty * 8 + i];
#pragma unroll
            for (int j = 0; j < 8; j++) rb[j] = Bs[k][tx * 8 + j];
#pragma unroll
            for (int i = 0; i < 8; i++)
#pragma unroll
                for (int j = 0; j < 8; j++) acc[i][j] += ra[i] * rb[j];
        }
        __syncthreads();
    }

#pragma unroll
    for (int i = 0; i < 8; i++) {
        int r = m0 + ty * 8 + i;
        float* orow = g_t + (size_t)r * N + n0;
#pragma unroll
        for (int j = 0; j < 8; j++) {
            float v = acc[i][j] + bias[n0 + tx * 8 + j];
            orow[tx * 8 + j] = gelu_exact(v);
        }
    }
}

// ---------------- router: softmax(t @ sw_W + sw_b), argmax, pmax ----------------
__global__ void router_kernel(const float* __restrict__ swW,
                              const float* __restrict__ swb)
{
    int tok = blockIdx.x;
    int tid = threadIdx.x;
    const float* tr = g_t + (size_t)tok * D_MODEL;

    float a0 = 0.f, a1 = 0.f, a2 = 0.f, a3 = 0.f;
    for (int k = tid; k < D_MODEL; k += 256) {
        float tv = tr[k];
        const float* w = swW + (size_t)k * NEXP;
        a0 += tv * w[0]; a1 += tv * w[1]; a2 += tv * w[2]; a3 += tv * w[3];
    }
    __shared__ float red[4][256];
    red[0][tid] = a0; red[1][tid] = a1; red[2][tid] = a2; red[3][tid] = a3;
    __syncthreads();
    for (int o = 128; o > 0; o >>= 1) {
        if (tid < o) {
            red[0][tid] += red[0][tid + o];
            red[1][tid] += red[1][tid + o];
            red[2][tid] += red[2][tid + o];
            red[3][tid] += red[3][tid + o];
        }
        __syncthreads();
    }
    if (tid == 0) {
        float l[NEXP];
        float mx = -1e30f; int arg = 0;
        for (int e = 0; e < NEXP; e++) {
            l[e] = red[e][0] + swb[e];
            if (l[e] > mx) { mx = l[e]; arg = e; }
        }
        float s = 0.f, p[NEXP];
        for (int e = 0; e < NEXP; e++) { p[e] = expf(l[e] - mx); s += p[e]; }
        float inv = 1.0f / s;
        for (int e = 0; e < NEXP; e++) g_probs[(size_t)tok * NEXP + e] = p[e] * inv;
        g_routes[tok] = arg;
        g_pmax[tok] = inv;   // p[arg] = 1
    }
}

// ---------------- probsum (deterministic tree) ----------------
__global__ void probsum_kernel()
{
    int e = blockIdx.x;
    int tid = threadIdx.x;
    float s = 0.f;
    for (int t = tid; t < T_TOK; t += 256) s += g_probs[(size_t)t * NEXP + e];
    __shared__ float red[256];
    red[tid] = s; __syncthreads();
    for (int o = 128; o > 0; o >>= 1) { if (tid < o) red[tid] += red[tid + o]; __syncthreads(); }
    if (tid == 0) g_probsum[e] = red[0];
}

// ---------------- capacity scan (single block, deterministic token order) ----------------
__global__ void scan_kernel()
{
    __shared__ int cnt[256][NEXP];
    int tid = threadIdx.x;
    const int CHUNK = T_TOK / 256;   // 36
    int base = tid * CHUNK;

    int c[NEXP] = {0, 0, 0, 0};
    for (int i = 0; i < CHUNK; i++) c[g_routes[base + i]]++;
    for (int e = 0; e < NEXP; e++) cnt[tid][e] = c[e];
    __syncthreads();

    if (tid == 0) {
        int run[NEXP] = {0, 0, 0, 0};
        for (int th = 0; th < 256; th++)
            for (int e = 0; e < NEXP; e++) {
                int tmp = cnt[th][e];
                cnt[th][e] = run[e];
                run[e] += tmp;
            }
        int nd = 0;
        for (int e = 0; e < NEXP; e++) {
            g_counts[e] = (float)run[e];
            int mf = run[e] < CAP ? run[e] : CAP;
            g_Mfill[e] = mf;
            nd += run[e] - mf;
        }
        g_ndrop[0] = (float)nd;
    }
    __syncthreads();

    int off[NEXP];
    for (int e = 0; e < NEXP; e++) off[e] = cnt[tid][e];
    for (int i = 0; i < CHUNK; i++) {
        int tok = base + i;
        int e = g_routes[tok];
        int p = off[e]++;
        int keep = (p < CAP) ? 1 : 0;
        g_keep[tok] = keep;
        if (keep) g_slot2tok[e * CAP + p] = tok;
    }
}

// ---------------- expert GEMMs ----------------
// MODE 1: h[slot] = gelu(t[tok] @ W1[e] + b1[e])   K=2048, N=8192, gathered A
// MODE 2: out[tok] = (h[slot] @ W2[e] + b2[e]) * pmax[tok]   K=8192, N=2048
template<int MODE>
__global__ void expert_gemm(const float* __restrict__ Wall,
                            const float* __restrict__ ball,
                            float* __restrict__ out)
{
    const int K = (MODE == 1) ? D_MODEL : H_FF;
    const int N = (MODE == 1) ? H_FF : D_MODEL;

    int e = blockIdx.z;
    int mfill = g_Mfill[e];
    int m0 = blockIdx.y * 128;
    if (m0 >= mfill) return;
    int n0 = blockIdx.x * 128;

    const float* W    = Wall + (size_t)e * K * N;
    const float* bias = ball + (size_t)e * N;

    __shared__ float As[8][128];
    __shared__ float Bs[8][128];

    int tid = threadIdx.x;
    int aRow = tid >> 1;
    int aCol = (tid & 1) * 4;
    int bRow = tid >> 5;
    int bCol = (tid & 31) * 4;
    int ty = tid >> 4, tx = tid & 15;

    int gRow = m0 + aRow;
    bool aValid = gRow < mfill;
    const float* aPtr = nullptr;
    if (aValid) {
        if (MODE == 1) {
            int tok = g_slot2tok[e * CAP + gRow];
            aPtr = g_t + (size_t)tok * K + aCol;
        } else {
            aPtr = g_h + ((size_t)e * CAP + gRow) * K + aCol;
        }
    }

    float acc[8][8];
#pragma unroll
    for (int i = 0; i < 8; i++)
#pragma unroll
        for (int j = 0; j < 8; j++) acc[i][j] = 0.f;

    for (int k0 = 0; k0 < K; k0 += 8) {
        float4 av = aValid ? *reinterpret_cast<const float4*>(aPtr + k0)
                           : make_float4(0.f, 0.f, 0.f, 0.f);
        float4 bv = *reinterpret_cast<const float4*>(&W[(size_t)(k0 + bRow) * N + n0 + bCol]);
        As[aCol + 0][aRow] = av.x; As[aCol + 1][aRow] = av.y;
        As[aCol + 2][aRow] = av.z; As[aCol + 3][aRow] = av.w;
        *reinterpret_cast<float4*>(&Bs[bRow][bCol]) = bv;
        __syncthreads();
#pragma unroll
        for (int k = 0; k < 8; k++) {
            float ra[8], rb[8];
#pragma unroll
            for (int i = 0; i < 8; i++) ra[i] = As[k][ty * 8 + i];
#pragma unroll
            for (int j = 0; j < 8; j++) rb[j] = Bs[k][tx * 8 + j];
#pragma unroll
            for (int i = 0; i < 8; i++)
#pragma unroll
                for (int j = 0; j < 8; j++) acc[i][j] += ra[i] * rb[j];
        }
        __syncthreads();
    }

#pragma unroll
    for (int i = 0; i < 8; i++) {
        int r = m0 + ty * 8 + i;
        if (r >= mfill) continue;
        if (MODE == 1) {
            float* orow = g_h + ((size_t)e * CAP + r) * N + n0;
#pragma unroll
            for (int j = 0; j < 8; j++) {
                float v = acc[i][j] + bias[n0 + tx * 8 + j];
                orow[tx * 8 + j] = gelu_exact(v);
            }
        } else {
            int tok = g_slot2tok[e * CAP + r];
            float pm = g_pmax[tok];
            float* orow = out + (size_t)tok * N + n0;
#pragma unroll
            for (int j = 0; j < 8; j++) {
                float v = acc[i][j] + bias[n0 + tx * 8 + j];
                orow[tx * 8 + j] = v * pm;
            }
        }
    }
}

// ---------------- dropped tokens: out = t * pmax ----------------
__global__ void dropped_kernel(float* __restrict__ out)
{
    int tok = blockIdx.x;
    if (g_keep[tok]) return;
    float pm = g_pmax[tok];
    const float* tr = g_t + (size_t)tok * D_MODEL;
    float* orow = out + (size_t)tok * D_MODEL;
    for (int c = threadIdx.x; c < D_MODEL; c += 256) orow[c] = tr[c] * pm;
}

// ---------------- extras: counts, probsum, n_dropped, pmax ----------------
__global__ void extras_kernel(float* __restrict__ out, int out_size)
{
    int i = blockIdx.x * 256 + threadIdx.x;
    if (i >= OUT_EXTRAS_N) return;
    long long off = (long long)OUT_COUNTS + i;
    if (off >= (long long)out_size) return;
    float v;
    if (i < 4)       v = g_counts[i];
    else if (i < 8)  v = g_probsum[i - 4];
    else if (i == 8) v = g_ndrop[0];
    else             v = g_pmax[i - 9];
    out[off] = v;
}

// ---------------- launch ----------------
extern "C" void kernel_launch(void* const* d_in, const int* in_sizes, int n_in,
                              void* d_out, int out_size)
{
    const float* x     = (const float*)d_in[0];
    const float* ln_g  = (const float*)d_in[1];
    const float* ln_b  = (const float*)d_in[2];
    const float* pre_W = (const float*)d_in[3];
    const float* pre_b = (const float*)d_in[4];
    const float* sw_W  = (const float*)d_in[5];
    const float* sw_b  = (const float*)d_in[6];
    const float* W1    = (const float*)d_in[7];
    const float* b1    = (const float*)d_in[8];
    const float* W2    = (const float*)d_in[9];
    const float* b2    = (const float*)d_in[10];
    float* out = (float*)d_out;

    ln_kernel<<<T_TOK, 256>>>(x, ln_g, ln_b);
    pre_gemm<<<dim3(D_MODEL / 128, T_TOK / 128), 256>>>(pre_W, pre_b);
    router_kernel<<<T_TOK, 256>>>(sw_W, sw_b);
    probsum_kernel<<<NEXP, 256>>>();
    scan_kernel<<<1, 256>>>();
    expert_gemm<1><<<dim3(H_FF / 128, CAP / 128, NEXP), 256>>>(W1, b1, nullptr);
    expert_gemm<2><<<dim3(D_MODEL / 128, CAP / 128, NEXP), 256>>>(W2, b2, out);
    dropped_kernel<<<T_TOK, 256>>>(out);
    extras_kernel<<<(OUT_EXTRAS_N + 255) / 256, 256>>>(out, out_size);
}

// round 4
// speedup vs baseline: 2.9329x; 2.9329x over previous
#include <cuda_runtime.h>
#include <math.h>
#include <stdint.h>

// ---------------- problem dims (fixed) ----------------
#define BATCH   16
#define SEQ     576
#define T_TOK   9216
#define D_IN    1024
#define D_MODEL 2048
#define NEXP    4
#define H_FF    8192
#define CAP     3456
#define ECAP    (NEXP*CAP)      // 13824

#define OUT_COUNTS  (T_TOK*D_MODEL)
#define OUT_EXTRAS_N 9225

// ---------------- scratch ----------------
__device__ float g_xn[(size_t)T_TOK * D_IN];
__device__ float g_t [(size_t)T_TOK * D_MODEL];
__device__ float g_probs[(size_t)T_TOK * NEXP];
__device__ float g_pmax [T_TOK];
__device__ int   g_routes[T_TOK];
__device__ int   g_keep  [T_TOK];
__device__ int   g_slot2tok[ECAP];
__device__ int   g_Mfill[NEXP];
__device__ float g_counts[NEXP];
__device__ float g_probsum[NEXP];
__device__ float g_ndrop[1];
__device__ float g_eb[(size_t)ECAP * D_MODEL];           // gathered tokens (tf32-rounded)
__device__ float g_h [(size_t)ECAP * H_FF];              // hidden (tf32-rounded)
__device__ float g_W1r[(size_t)NEXP * D_MODEL * H_FF];   // tf32-rounded W1 [e][k][n]
__device__ float g_W2r[(size_t)NEXP * H_FF * D_MODEL];   // tf32-rounded W2 [e][k][n]

__device__ __forceinline__ float gelu_exact(float x) {
    return 0.5f * x * (1.0f + erff(x * 0.70710678118654752f));
}
__device__ __forceinline__ uint32_t f2tf32(float f) {
    uint32_t r;
    asm("cvt.rna.tf32.f32 %0, %1;" : "=r"(r) : "f"(f));
    return r;
}
__device__ __forceinline__ float f2tf32f(float f) {
    return __uint_as_float(f2tf32(f));
}
__device__ __forceinline__ uint32_t smem_u32(const void* p) {
    uint32_t a;
    asm("{ .reg .u64 t; cvta.to.shared.u64 t, %1; cvt.u32.u64 %0, t; }" : "=r"(a) : "l"(p));
    return a;
}
__device__ __forceinline__ void cp16(uint32_t dst, const void* src) {
    asm volatile("cp.async.cg.shared.global [%0], [%1], 16;" :: "r"(dst), "l"(src) : "memory");
}
__device__ __forceinline__ void cp_commit() { asm volatile("cp.async.commit_group;" ::: "memory"); }
template<int N> __device__ __forceinline__ void cp_wait() {
    asm volatile("cp.async.wait_group %0;" :: "n"(N) : "memory");
}
__device__ __forceinline__ void mma_tf32(float& c0, float& c1, float& c2, float& c3,
                                         uint32_t a0, uint32_t a1, uint32_t a2, uint32_t a3,
                                         uint32_t b0, uint32_t b1) {
    asm volatile(
        "mma.sync.aligned.m16n8k8.row.col.f32.tf32.tf32.f32 "
        "{%0,%1,%2,%3}, {%4,%5,%6,%7}, {%8,%9}, {%0,%1,%2,%3};"
        : "+f"(c0), "+f"(c1), "+f"(c2), "+f"(c3)
        : "r"(a0), "r"(a1), "r"(a2), "r"(a3), "r"(b0), "r"(b1));
}

// ---------------- LayerNorm ----------------
__global__ void ln_kernel(const float* __restrict__ x,
                          const float* __restrict__ g,
                          const float* __restrict__ b)
{
    int tok = blockIdx.x, tid = threadIdx.x;
    const float* xr = x + (size_t)tok * D_IN;
    __shared__ float red[256];
    float s = 0.f;
    for (int i = tid; i < D_IN; i += 256) s += xr[i];
    red[tid] = s; __syncthreads();
    for (int o = 128; o > 0; o >>= 1) { if (tid < o) red[tid] += red[tid + o]; __syncthreads(); }
    float mu = red[0] * (1.0f / D_IN);
    __syncthreads();
    float v = 0.f;
    for (int i = tid; i < D_IN; i += 256) { float d = xr[i] - mu; v += d * d; }
    red[tid] = v; __syncthreads();
    for (int o = 128; o > 0; o >>= 1) { if (tid < o) red[tid] += red[tid + o]; __syncthreads(); }
    float rstd = rsqrtf(red[0] * (1.0f / D_IN) + 1e-5f);
    float* xo = g_xn + (size_t)tok * D_IN;
    for (int i = tid; i < D_IN; i += 256)
        xo[i] = (xr[i] - mu) * rstd * g[i] + b[i];
}

// ---------------- pre-linear GEMM (fp32 FFMA, exact — feeds router argmax) ----------------
__global__ void pre_gemm(const float* __restrict__ W, const float* __restrict__ bias)
{
    const int K = D_IN, N = D_MODEL;
    int m0 = blockIdx.y * 128, n0 = blockIdx.x * 128, tid = threadIdx.x;
    __shared__ float As[8][128];
    __shared__ float Bs[8][128];
    int aRow = tid >> 1, aCol = (tid & 1) * 4;
    int bRow = tid >> 5, bCol = (tid & 31) * 4;
    int ty = tid >> 4, tx = tid & 15;
    const float* aPtr = g_xn + (size_t)(m0 + aRow) * K + aCol;
    float acc[8][8];
#pragma unroll
    for (int i = 0; i < 8; i++)
#pragma unroll
        for (int j = 0; j < 8; j++) acc[i][j] = 0.f;
    for (int k0 = 0; k0 < K; k0 += 8) {
        float4 av = *reinterpret_cast<const float4*>(aPtr + k0);
        float4 bv = *reinterpret_cast<const float4*>(&W[(size_t)(k0 + bRow) * N + n0 + bCol]);
        As[aCol + 0][aRow] = av.x; As[aCol + 1][aRow] = av.y;
        As[aCol + 2][aRow] = av.z; As[aCol + 3][aRow] = av.w;
        *reinterpret_cast<float4*>(&Bs[bRow][bCol]) = bv;
        __syncthreads();
#pragma unroll
        for (int k = 0; k < 8; k++) {
            float ra[8], rb[8];
#pragma unroll
            for (int i = 0; i < 8; i++) ra[i] = As[k][ty * 8 + i];
#pragma unroll
            for (int j = 0; j < 8; j++) rb[j] = Bs[k][tx * 8 + j];
#pragma unroll
            for (int i = 0; i < 8; i++)
#pragma unroll
                for (int j = 0; j < 8; j++) acc[i][j] += ra[i] * rb[j];
        }
        __syncthreads();
    }
#pragma unroll
    for (int i = 0; i < 8; i++) {
        int r = m0 + ty * 8 + i;
        float* orow = g_t + (size_t)r * N + n0;
#pragma unroll
        for (int j = 0; j < 8; j++) {
            float v = acc[i][j] + bias[n0 + tx * 8 + j];
            orow[tx * 8 + j] = gelu_exact(v);
        }
    }
}

// ---------------- router ----------------
__global__ void router_kernel(const float* __restrict__ swW, const float* __restrict__ swb)
{
    int tok = blockIdx.x, tid = threadIdx.x;
    const float* tr = g_t + (size_t)tok * D_MODEL;
    float a0 = 0.f, a1 = 0.f, a2 = 0.f, a3 = 0.f;
    for (int k = tid; k < D_MODEL; k += 256) {
        float tv = tr[k];
        const float* w = swW + (size_t)k * NEXP;
        a0 += tv * w[0]; a1 += tv * w[1]; a2 += tv * w[2]; a3 += tv * w[3];
    }
    __shared__ float red[4][256];
    red[0][tid] = a0; red[1][tid] = a1; red[2][tid] = a2; red[3][tid] = a3;
    __syncthreads();
    for (int o = 128; o > 0; o >>= 1) {
        if (tid < o) {
            red[0][tid] += red[0][tid + o]; red[1][tid] += red[1][tid + o];
            red[2][tid] += red[2][tid + o]; red[3][tid] += red[3][tid + o];
        }
        __syncthreads();
    }
    if (tid == 0) {
        float l[NEXP]; float mx = -1e30f; int arg = 0;
        for (int e = 0; e < NEXP; e++) {
            l[e] = red[e][0] + swb[e];
            if (l[e] > mx) { mx = l[e]; arg = e; }
        }
        float s = 0.f, p[NEXP];
        for (int e = 0; e < NEXP; e++) { p[e] = expf(l[e] - mx); s += p[e]; }
        float inv = 1.0f / s;
        for (int e = 0; e < NEXP; e++) g_probs[(size_t)tok * NEXP + e] = p[e] * inv;
        g_routes[tok] = arg;
        g_pmax[tok] = inv;
    }
}

__global__ void probsum_kernel()
{
    int e = blockIdx.x, tid = threadIdx.x;
    float s = 0.f;
    for (int t = tid; t < T_TOK; t += 256) s += g_probs[(size_t)t * NEXP + e];
    __shared__ float red[256];
    red[tid] = s; __syncthreads();
    for (int o = 128; o > 0; o >>= 1) { if (tid < o) red[tid] += red[tid + o]; __syncthreads(); }
    if (tid == 0) g_probsum[e] = red[0];
}

// ---------------- capacity scan ----------------
__global__ void scan_kernel()
{
    __shared__ int cnt[256][NEXP];
    int tid = threadIdx.x;
    const int CHUNK = T_TOK / 256;
    int base = tid * CHUNK;
    int c[NEXP] = {0, 0, 0, 0};
    for (int i = 0; i < CHUNK; i++) c[g_routes[base + i]]++;
    for (int e = 0; e < NEXP; e++) cnt[tid][e] = c[e];
    __syncthreads();
    if (tid == 0) {
        int run[NEXP] = {0, 0, 0, 0};
        for (int th = 0; th < 256; th++)
            for (int e = 0; e < NEXP; e++) {
                int tmp = cnt[th][e]; cnt[th][e] = run[e]; run[e] += tmp;
            }
        int nd = 0;
        for (int e = 0; e < NEXP; e++) {
            g_counts[e] = (float)run[e];
            int mf = run[e] < CAP ? run[e] : CAP;
            g_Mfill[e] = mf;
            nd += run[e] - mf;
        }
        g_ndrop[0] = (float)nd;
    }
    __syncthreads();
    int off[NEXP];
    for (int e = 0; e < NEXP; e++) off[e] = cnt[tid][e];
    for (int i = 0; i < CHUNK; i++) {
        int tok = base + i;
        int e = g_routes[tok];
        int p = off[e]++;
        int keep = (p < CAP) ? 1 : 0;
        g_keep[tok] = keep;
        if (keep) g_slot2tok[e * CAP + p] = tok;
    }
}

// ---------------- dispatch gather (tf32-rounded): g_eb[slot] = rna(g_t[tok]) ----------------
__global__ void dispatch_kernel()
{
    int slot = blockIdx.x;
    int e = slot / CAP, p = slot % CAP;
    if (p >= g_Mfill[e]) return;
    int tok = g_slot2tok[slot];
    float4* dst = reinterpret_cast<float4*>(g_eb + (size_t)slot * D_MODEL);
    const float4* src = reinterpret_cast<const float4*>(g_t + (size_t)tok * D_MODEL);
    for (int i = threadIdx.x; i < D_MODEL / 4; i += 128) {
        float4 v = src[i];
        v.x = f2tf32f(v.x); v.y = f2tf32f(v.y);
        v.z = f2tf32f(v.z); v.w = f2tf32f(v.w);
        dst[i] = v;
    }
}

// ---------------- weight rounding to tf32 (RNE) ----------------
__global__ void round_w(const float* __restrict__ in, float* __restrict__ out, size_t n4)
{
    size_t i = (size_t)blockIdx.x * blockDim.x + threadIdx.x;
    size_t stride = (size_t)gridDim.x * blockDim.x;
    const float4* I = reinterpret_cast<const float4*>(in);
    float4* O = reinterpret_cast<float4*>(out);
    for (; i < n4; i += stride) {
        float4 v = I[i];
        v.x = f2tf32f(v.x); v.y = f2tf32f(v.y);
        v.z = f2tf32f(v.z); v.w = f2tf32f(v.w);
        O[i] = v;
    }
}

// ---------------- mma.sync tf32 expert GEMMs ----------------
// CTA tile 128x128x32, 8 warps (2 m x 4 n), warp tile 64x32.
#define BM 128
#define BN 128
#define BK 32
#define ASTR 36                  // padded A smem stride (floats): banks 4g+tig distinct
#define BSTR 136                 // padded B smem stride (floats): banks 8tig+g distinct
#define A_FLOATS (BM * ASTR)     // 4608
#define B_FLOATS (BK * BSTR)     // 4352
#define NSTAGE 3
#define SMEM_MOE (NSTAGE * (A_FLOATS + B_FLOATS) * 4)   // 107520 B

// MODE 1: g_h[slot] = rna(gelu(g_eb[slot] @ W1r[e] + b1))   K=2048, NT=8192
// MODE 2: out[tok]  = (g_h[slot] @ W2r[e] + b2) * pmax       K=8192, NT=2048
template<int MODE>
__global__ void __launch_bounds__(256, 1)
moe_mma(const float* __restrict__ bias_all, float* __restrict__ out)
{
    const int K  = (MODE == 1) ? D_MODEL : H_FF;
    const int NT = (MODE == 1) ? H_FF : D_MODEL;
    const int C  = K / BK;

    int e = blockIdx.z;
    int mfill = g_Mfill[e];
    int m0 = blockIdx.y * BM;
    if (m0 >= mfill) return;
    int n0 = blockIdx.x * BN;

    extern __shared__ float smem[];
    float* Abuf = smem;
    float* Bbuf = smem + NSTAGE * A_FLOATS;
    uint32_t sA = smem_u32(Abuf);
    uint32_t sB = smem_u32(Bbuf);

    int tid = threadIdx.x;
    int w = tid >> 5, lane = tid & 31;
    int wm = w >> 2, wn = w & 3;           // warp tile: rows wm*64, cols wn*32
    int g = lane >> 2, tig = lane & 3;

    const float* Abase = ((MODE == 1) ? g_eb : g_h) + (size_t)(e * CAP + m0) * K;
    const float* Bbase = ((MODE == 1) ? g_W1r : g_W2r) + (size_t)e * K * NT;

    // cp.async source/dest precompute
    // A: 4 chunks/thread: idx = i*256+tid; row = idx>>3, kc = idx&7
    const float* a_src[4]; uint32_t a_dst[4];
#pragma unroll
    for (int i = 0; i < 4; i++) {
        int idx = i * 256 + tid;
        int row = idx >> 3, kc = idx & 7;
        a_src[i] = Abase + (size_t)row * K + kc * 4;
        a_dst[i] = (uint32_t)(row * ASTR + kc * 4) * 4u;
    }
    // B: 4 chunks/thread: idx = i*256+tid; kr = idx>>5, nc = idx&31
    const float* b_src[4]; uint32_t b_dst[4];
#pragma unroll
    for (int i = 0; i < 4; i++) {
        int idx = i * 256 + tid;
        int kr = idx >> 5, nc = idx & 31;
        b_src[i] = Bbase + (size_t)kr * NT + n0 + nc * 4;
        b_dst[i] = (uint32_t)(kr * BSTR + nc * 4) * 4u;
    }

#define LOAD_STAGE(c) do {                                                   \
        int s_ = (c) % NSTAGE;                                               \
        uint32_t aS = sA + (uint32_t)(s_ * A_FLOATS * 4);                    \
        uint32_t bS = sB + (uint32_t)(s_ * B_FLOATS * 4);                    \
        _Pragma("unroll")                                                    \
        for (int i = 0; i < 4; i++) cp16(aS + a_dst[i], a_src[i] + (c) * BK); \
        _Pragma("unroll")                                                    \
        for (int i = 0; i < 4; i++) cp16(bS + b_dst[i], b_src[i] + (size_t)(c) * BK * NT); \
        cp_commit();                                                         \
    } while (0)

    float acc[4][4][4];
#pragma unroll
    for (int mt = 0; mt < 4; mt++)
#pragma unroll
        for (int nt = 0; nt < 4; nt++)
#pragma unroll
            for (int q = 0; q < 4; q++) acc[mt][nt][q] = 0.f;

    LOAD_STAGE(0);
    LOAD_STAGE(1);

    for (int c = 0; c < C; c++) {
        cp_wait<1>();
        __syncthreads();
        if (c + 2 < C) LOAD_STAGE(c + 2);
        else cp_commit();   // keep group count in sync

        int s = c % NSTAGE;
        const float* As = Abuf + s * A_FLOATS;
        const float* Bs = Bbuf + s * B_FLOATS;
        const uint32_t* Au = reinterpret_cast<const uint32_t*>(As);
        const uint32_t* Bu = reinterpret_cast<const uint32_t*>(Bs);

#pragma unroll
        for (int ks = 0; ks < 4; ks++) {
            uint32_t af[4][4];
#pragma unroll
            for (int mt = 0; mt < 4; mt++) {
                int r = wm * 64 + mt * 16 + g;
                int base = r * ASTR + ks * 8 + tig;
                af[mt][0] = Au[base];
                af[mt][1] = Au[base + 8 * ASTR];
                af[mt][2] = Au[base + 4];
                af[mt][3] = Au[base + 8 * ASTR + 4];
            }
            uint32_t bf[4][2];
#pragma unroll
            for (int nt = 0; nt < 4; nt++) {
                int base = (ks * 8 + tig) * BSTR + wn * 32 + nt * 8 + g;
                bf[nt][0] = Bu[base];
                bf[nt][1] = Bu[base + 4 * BSTR];
            }
#pragma unroll
            for (int mt = 0; mt < 4; mt++)
#pragma unroll
                for (int nt = 0; nt < 4; nt++)
                    mma_tf32(acc[mt][nt][0], acc[mt][nt][1], acc[mt][nt][2], acc[mt][nt][3],
                             af[mt][0], af[mt][1], af[mt][2], af[mt][3],
                             bf[nt][0], bf[nt][1]);
        }
        __syncthreads();
    }

    // epilogue: c0,c1 at (row, col..col+1); c2,c3 at (row+8, col..col+1)
    const float* bias = bias_all + (size_t)e * NT + n0;
#pragma unroll
    for (int mt = 0; mt < 4; mt++) {
        int r0 = m0 + wm * 64 + mt * 16 + g;
#pragma unroll
        for (int half = 0; half < 2; half++) {
            int r = r0 + half * 8;
            if (r >= mfill) continue;
            float* orow;
            float pm = 1.0f;
            if (MODE == 1) {
                orow = g_h + (size_t)(e * CAP + r) * H_FF + n0;
            } else {
                int tok = g_slot2tok[e * CAP + r];
                pm = g_pmax[tok];
                orow = out + (size_t)tok * D_MODEL + n0;
            }
#pragma unroll
            for (int nt = 0; nt < 4; nt++) {
                int col = wn * 32 + nt * 8 + 2 * tig;
                float v0 = acc[mt][nt][half * 2 + 0] + bias[col];
                float v1 = acc[mt][nt][half * 2 + 1] + bias[col + 1];
                float2 o;
                if (MODE == 1) {
                    o.x = f2tf32f(gelu_exact(v0));
                    o.y = f2tf32f(gelu_exact(v1));
                } else {
                    o.x = v0 * pm;
                    o.y = v1 * pm;
                }
                *reinterpret_cast<float2*>(orow + col) = o;
            }
        }
    }
#undef LOAD_STAGE
}

// ---------------- dropped tokens ----------------
__global__ void dropped_kernel(float* __restrict__ out)
{
    int tok = blockIdx.x;
    if (g_keep[tok]) return;
    float pm = g_pmax[tok];
    const float* tr = g_t + (size_t)tok * D_MODEL;
    float* orow = out + (size_t)tok * D_MODEL;
    for (int c = threadIdx.x; c < D_MODEL; c += 256) orow[c] = tr[c] * pm;
}

// ---------------- extras ----------------
__global__ void extras_kernel(float* __restrict__ out, int out_size)
{
    int i = blockIdx.x * 256 + threadIdx.x;
    if (i >= OUT_EXTRAS_N) return;
    long long off = (long long)OUT_COUNTS + i;
    if (off >= (long long)out_size) return;
    float v;
    if (i < 4)       v = g_counts[i];
    else if (i < 8)  v = g_probsum[i - 4];
    else if (i == 8) v = g_ndrop[0];
    else             v = g_pmax[i - 9];
    out[off] = v;
}

// ---------------- launch ----------------
extern "C" void kernel_launch(void* const* d_in, const int* in_sizes, int n_in,
                              void* d_out, int out_size)
{
    const float* x     = (const float*)d_in[0];
    const float* ln_g  = (const float*)d_in[1];
    const float* ln_b  = (const float*)d_in[2];
    const float* pre_W = (const float*)d_in[3];
    const float* pre_b = (const float*)d_in[4];
    const float* sw_W  = (const float*)d_in[5];
    const float* sw_b  = (const float*)d_in[6];
    const float* W1    = (const float*)d_in[7];
    const float* b1    = (const float*)d_in[8];
    const float* W2    = (const float*)d_in[9];
    const float* b2    = (const float*)d_in[10];
    float* out = (float*)d_out;

    static float* d_W1r = nullptr;
    if (!d_W1r) {
        cudaGetSymbolAddress((void**)&d_W1r, g_W1r);   // host-side, not in graph
        cudaFuncSetAttribute(moe_mma<1>, cudaFuncAttributeMaxDynamicSharedMemorySize, SMEM_MOE);
        cudaFuncSetAttribute(moe_mma<2>, cudaFuncAttributeMaxDynamicSharedMemorySize, SMEM_MOE);
    }
    float* d_W2r = nullptr;
    cudaGetSymbolAddress((void**)&d_W2r, g_W2r);

    const size_t WN4 = (size_t)NEXP * D_MODEL * H_FF / 4;

    ln_kernel<<<T_TOK, 256>>>(x, ln_g, ln_b);
    pre_gemm<<<dim3(D_MODEL / 128, T_TOK / 128), 256>>>(pre_W, pre_b);
    router_kernel<<<T_TOK, 256>>>(sw_W, sw_b);
    probsum_kernel<<<NEXP, 256>>>();
    scan_kernel<<<1, 256>>>();
    dispatch_kernel<<<ECAP, 128>>>();
    round_w<<<1184, 256>>>(W1, d_W1r, WN4);
    round_w<<<1184, 256>>>(W2, d_W2r, WN4);
    moe_mma<1><<<dim3(H_FF / BN, CAP / BM, NEXP), 256, SMEM_MOE>>>(b1, nullptr);
    moe_mma<2><<<dim3(D_MODEL / BN, CAP / BM, NEXP), 256, SMEM_MOE>>>(b2, out);
    dropped_kernel<<<T_TOK, 256>>>(out);
    extras_kernel<<<(OUT_EXTRAS_N + 255) / 256, 256>>>(out, out_size);
}

// round 5
// speedup vs baseline: 3.0342x; 1.0345x over previous
#include <cuda_runtime.h>
#include <math.h>
#include <stdint.h>

// ---------------- problem dims (fixed) ----------------
#define BATCH   16
#define SEQ     576
#define T_TOK   9216
#define D_IN    1024
#define D_MODEL 2048
#define NEXP    4
#define H_FF    8192
#define CAP     3456
#define ECAP    (NEXP*CAP)      // 13824

#define OUT_COUNTS  (T_TOK*D_MODEL)
#define OUT_EXTRAS_N 9225

// ---------------- scratch ----------------
__device__ float g_xn[(size_t)T_TOK * D_IN];
__device__ float g_t [(size_t)T_TOK * D_MODEL];
__device__ float g_probs[(size_t)T_TOK * NEXP];
__device__ float g_pmax [T_TOK];
__device__ int   g_routes[T_TOK];
__device__ int   g_keep  [T_TOK];
__device__ int   g_slot2tok[ECAP];
__device__ int   g_Mfill[NEXP];
__device__ float g_counts[NEXP];
__device__ float g_probsum[NEXP];
__device__ float g_ndrop[1];
__device__ float g_eb[(size_t)ECAP * D_MODEL];           // gathered tokens (tf32-rounded)
__device__ float g_h [(size_t)ECAP * H_FF];              // hidden (tf32-rounded)

__device__ __forceinline__ float gelu_exact(float x) {
    return 0.5f * x * (1.0f + erff(x * 0.70710678118654752f));
}
__device__ __forceinline__ uint32_t f2tf32(float f) {
    uint32_t r;
    asm("cvt.rna.tf32.f32 %0, %1;" : "=r"(r) : "f"(f));
    return r;
}
__device__ __forceinline__ float f2tf32f(float f) {
    return __uint_as_float(f2tf32(f));
}
__device__ __forceinline__ uint32_t smem_u32(const void* p) {
    uint32_t a;
    asm("{ .reg .u64 t; cvta.to.shared.u64 t, %1; cvt.u32.u64 %0, t; }" : "=r"(a) : "l"(p));
    return a;
}
__device__ __forceinline__ void cp16(uint32_t dst, const void* src) {
    asm volatile("cp.async.cg.shared.global [%0], [%1], 16;" :: "r"(dst), "l"(src) : "memory");
}
__device__ __forceinline__ void cp_commit() { asm volatile("cp.async.commit_group;" ::: "memory"); }
template<int N> __device__ __forceinline__ void cp_wait() {
    asm volatile("cp.async.wait_group %0;" :: "n"(N) : "memory");
}
__device__ __forceinline__ void mma_tf32(float& c0, float& c1, float& c2, float& c3,
                                         uint32_t a0, uint32_t a1, uint32_t a2, uint32_t a3,
                                         uint32_t b0, uint32_t b1) {
    asm volatile(
        "mma.sync.aligned.m16n8k8.row.col.f32.tf32.tf32.f32 "
        "{%0,%1,%2,%3}, {%4,%5,%6,%7}, {%8,%9}, {%0,%1,%2,%3};"
        : "+f"(c0), "+f"(c1), "+f"(c2), "+f"(c3)
        : "r"(a0), "r"(a1), "r"(a2), "r"(a3), "r"(b0), "r"(b1));
}

// ---------------- LayerNorm ----------------
__global__ void ln_kernel(const float* __restrict__ x,
                          const float* __restrict__ g,
                          const float* __restrict__ b)
{
    int tok = blockIdx.x, tid = threadIdx.x;
    const float* xr = x + (size_t)tok * D_IN;
    __shared__ float red[256];
    float s = 0.f;
    for (int i = tid; i < D_IN; i += 256) s += xr[i];
    red[tid] = s; __syncthreads();
    for (int o = 128; o > 0; o >>= 1) { if (tid < o) red[tid] += red[tid + o]; __syncthreads(); }
    float mu = red[0] * (1.0f / D_IN);
    __syncthreads();
    float v = 0.f;
    for (int i = tid; i < D_IN; i += 256) { float d = xr[i] - mu; v += d * d; }
    red[tid] = v; __syncthreads();
    for (int o = 128; o > 0; o >>= 1) { if (tid < o) red[tid] += red[tid + o]; __syncthreads(); }
    float rstd = rsqrtf(red[0] * (1.0f / D_IN) + 1e-5f);
    float* xo = g_xn + (size_t)tok * D_IN;
    for (int i = tid; i < D_IN; i += 256)
        xo[i] = (xr[i] - mu) * rstd * g[i] + b[i];
}

// ---------------- pre-linear GEMM (fp32 FFMA, exact — feeds router argmax) ----------------
__global__ void pre_gemm(const float* __restrict__ W, const float* __restrict__ bias)
{
    const int K = D_IN, N = D_MODEL;
    int m0 = blockIdx.y * 128, n0 = blockIdx.x * 128, tid = threadIdx.x;
    __shared__ float As[8][128];
    __shared__ float Bs[8][128];
    int aRow = tid >> 1, aCol = (tid & 1) * 4;
    int bRow = tid >> 5, bCol = (tid & 31) * 4;
    int ty = tid >> 4, tx = tid & 15;
    const float* aPtr = g_xn + (size_t)(m0 + aRow) * K + aCol;
    float acc[8][8];
#pragma unroll
    for (int i = 0; i < 8; i++)
#pragma unroll
        for (int j = 0; j < 8; j++) acc[i][j] = 0.f;
    for (int k0 = 0; k0 < K; k0 += 8) {
        float4 av = *reinterpret_cast<const float4*>(aPtr + k0);
        float4 bv = *reinterpret_cast<const float4*>(&W[(size_t)(k0 + bRow) * N + n0 + bCol]);
        As[aCol + 0][aRow] = av.x; As[aCol + 1][aRow] = av.y;
        As[aCol + 2][aRow] = av.z; As[aCol + 3][aRow] = av.w;
        *reinterpret_cast<float4*>(&Bs[bRow][bCol]) = bv;
        __syncthreads();
#pragma unroll
        for (int k = 0; k < 8; k++) {
            float ra[8], rb[8];
#pragma unroll
            for (int i = 0; i < 8; i++) ra[i] = As[k][ty * 8 + i];
#pragma unroll
            for (int j = 0; j < 8; j++) rb[j] = Bs[k][tx * 8 + j];
#pragma unroll
            for (int i = 0; i < 8; i++)
#pragma unroll
                for (int j = 0; j < 8; j++) acc[i][j] += ra[i] * rb[j];
        }
        __syncthreads();
    }
#pragma unroll
    for (int i = 0; i < 8; i++) {
        int r = m0 + ty * 8 + i;
        float* orow = g_t + (size_t)r * N + n0;
#pragma unroll
        for (int j = 0; j < 8; j++) {
            float v = acc[i][j] + bias[n0 + tx * 8 + j];
            orow[tx * 8 + j] = gelu_exact(v);
        }
    }
}

// ---------------- router ----------------
__global__ void router_kernel(const float* __restrict__ swW, const float* __restrict__ swb)
{
    int tok = blockIdx.x, tid = threadIdx.x;
    const float* tr = g_t + (size_t)tok * D_MODEL;
    float a0 = 0.f, a1 = 0.f, a2 = 0.f, a3 = 0.f;
    for (int k = tid; k < D_MODEL; k += 256) {
        float tv = tr[k];
        const float* w = swW + (size_t)k * NEXP;
        a0 += tv * w[0]; a1 += tv * w[1]; a2 += tv * w[2]; a3 += tv * w[3];
    }
    __shared__ float red[4][256];
    red[0][tid] = a0; red[1][tid] = a1; red[2][tid] = a2; red[3][tid] = a3;
    __syncthreads();
    for (int o = 128; o > 0; o >>= 1) {
        if (tid < o) {
            red[0][tid] += red[0][tid + o]; red[1][tid] += red[1][tid + o];
            red[2][tid] += red[2][tid + o]; red[3][tid] += red[3][tid + o];
        }
        __syncthreads();
    }
    if (tid == 0) {
        float l[NEXP]; float mx = -1e30f; int arg = 0;
        for (int e = 0; e < NEXP; e++) {
            l[e] = red[e][0] + swb[e];
            if (l[e] > mx) { mx = l[e]; arg = e; }
        }
        float s = 0.f, p[NEXP];
        for (int e = 0; e < NEXP; e++) { p[e] = expf(l[e] - mx); s += p[e]; }
        float inv = 1.0f / s;
        for (int e = 0; e < NEXP; e++) g_probs[(size_t)tok * NEXP + e] = p[e] * inv;
        g_routes[tok] = arg;
        g_pmax[tok] = inv;
    }
}

__global__ void probsum_kernel()
{
    int e = blockIdx.x, tid = threadIdx.x;
    float s = 0.f;
    for (int t = tid; t < T_TOK; t += 256) s += g_probs[(size_t)t * NEXP + e];
    __shared__ float red[256];
    red[tid] = s; __syncthreads();
    for (int o = 128; o > 0; o >>= 1) { if (tid < o) red[tid] += red[tid + o]; __syncthreads(); }
    if (tid == 0) g_probsum[e] = red[0];
}

// ---------------- capacity scan ----------------
__global__ void scan_kernel()
{
    __shared__ int cnt[256][NEXP];
    int tid = threadIdx.x;
    const int CHUNK = T_TOK / 256;
    int base = tid * CHUNK;
    int c[NEXP] = {0, 0, 0, 0};
    for (int i = 0; i < CHUNK; i++) c[g_routes[base + i]]++;
    for (int e = 0; e < NEXP; e++) cnt[tid][e] = c[e];
    __syncthreads();
    if (tid == 0) {
        int run[NEXP] = {0, 0, 0, 0};
        for (int th = 0; th < 256; th++)
            for (int e = 0; e < NEXP; e++) {
                int tmp = cnt[th][e]; cnt[th][e] = run[e]; run[e] += tmp;
            }
        int nd = 0;
        for (int e = 0; e < NEXP; e++) {
            g_counts[e] = (float)run[e];
            int mf = run[e] < CAP ? run[e] : CAP;
            g_Mfill[e] = mf;
            nd += run[e] - mf;
        }
        g_ndrop[0] = (float)nd;
    }
    __syncthreads();
    int off[NEXP];
    for (int e = 0; e < NEXP; e++) off[e] = cnt[tid][e];
    for (int i = 0; i < CHUNK; i++) {
        int tok = base + i;
        int e = g_routes[tok];
        int p = off[e]++;
        int keep = (p < CAP) ? 1 : 0;
        g_keep[tok] = keep;
        if (keep) g_slot2tok[e * CAP + p] = tok;
    }
}

// ---------------- dispatch gather (tf32-rounded): g_eb[slot] = rna(g_t[tok]) ----------------
__global__ void dispatch_kernel()
{
    int slot = blockIdx.x;
    int e = slot / CAP, p = slot % CAP;
    if (p >= g_Mfill[e]) return;
    int tok = g_slot2tok[slot];
    float4* dst = reinterpret_cast<float4*>(g_eb + (size_t)slot * D_MODEL);
    const float4* src = reinterpret_cast<const float4*>(g_t + (size_t)tok * D_MODEL);
    for (int i = threadIdx.x; i < D_MODEL / 4; i += 128) {
        float4 v = src[i];
        v.x = f2tf32f(v.x); v.y = f2tf32f(v.y);
        v.z = f2tf32f(v.z); v.w = f2tf32f(v.w);
        dst[i] = v;
    }
}

// ---------------- mma.sync tf32 expert GEMMs ----------------
// CTA tile 128x128x32, 8 warps (2 m x 4 n), warp tile 64x32.
// 4-stage cp.async pipeline (prefetch depth 3), one __syncthreads per chunk.
// B is raw fp32 weight memory; cvt.rna.tf32 fused into fragment loads.
#define BM 128
#define BN 128
#define BK 32
#define ASTR 36                  // padded A smem stride (floats)
#define BSTR 136                 // padded B smem stride (floats)
#define A_FLOATS (BM * ASTR)     // 4608
#define B_FLOATS (BK * BSTR)     // 4352
#define NSTAGE 4
#define SMEM_MOE (NSTAGE * (A_FLOATS + B_FLOATS) * 4)   // 143360 B

// MODE 1: g_h[slot] = rna(gelu(g_eb[slot] @ W1[e] + b1))   K=2048, NT=8192
// MODE 2: out[tok]  = (g_h[slot] @ W2[e] + b2) * pmax       K=8192, NT=2048
template<int MODE>
__global__ void __launch_bounds__(256, 1)
moe_mma(const float* __restrict__ Wsrc, const float* __restrict__ bias_all,
        float* __restrict__ out)
{
    const int K  = (MODE == 1) ? D_MODEL : H_FF;
    const int NT = (MODE == 1) ? H_FF : D_MODEL;
    const int C  = K / BK;

    int e = blockIdx.z;
    int mfill = g_Mfill[e];
    int m0 = blockIdx.x * BM;          // m on x: wave working set fits L2
    if (m0 >= mfill) return;
    int n0 = blockIdx.y * BN;

    extern __shared__ float smem[];
    float* Abuf = smem;
    float* Bbuf = smem + NSTAGE * A_FLOATS;
    uint32_t sA = smem_u32(Abuf);
    uint32_t sB = smem_u32(Bbuf);

    int tid = threadIdx.x;
    int w = tid >> 5, lane = tid & 31;
    int wm = w >> 2, wn = w & 3;
    int g = lane >> 2, tig = lane & 3;

    const float* Abase = ((MODE == 1) ? g_eb : g_h) + (size_t)(e * CAP + m0) * K;
    const float* Bbase = Wsrc + (size_t)e * K * NT;

    const float* a_src[4]; uint32_t a_dst[4];
#pragma unroll
    for (int i = 0; i < 4; i++) {
        int idx = i * 256 + tid;
        int row = idx >> 3, kc = idx & 7;
        a_src[i] = Abase + (size_t)row * K + kc * 4;
        a_dst[i] = (uint32_t)(row * ASTR + kc * 4) * 4u;
    }
    const float* b_src[4]; uint32_t b_dst[4];
#pragma unroll
    for (int i = 0; i < 4; i++) {
        int idx = i * 256 + tid;
        int kr = idx >> 5, nc = idx & 31;
        b_src[i] = Bbase + (size_t)kr * NT + n0 + nc * 4;
        b_dst[i] = (uint32_t)(kr * BSTR + nc * 4) * 4u;
    }

#define LOAD_STAGE(c) do {                                                   \
        int s_ = (c) % NSTAGE;                                               \
        uint32_t aS = sA + (uint32_t)(s_ * A_FLOATS * 4);                    \
        uint32_t bS = sB + (uint32_t)(s_ * B_FLOATS * 4);                    \
        _Pragma("unroll")                                                    \
        for (int i = 0; i < 4; i++) cp16(aS + a_dst[i], a_src[i] + (c) * BK); \
        _Pragma("unroll")                                                    \
        for (int i = 0; i < 4; i++) cp16(bS + b_dst[i], b_src[i] + (size_t)(c) * BK * NT); \
        cp_commit();                                                         \
    } while (0)

    float acc[4][4][4];
#pragma unroll
    for (int mt = 0; mt < 4; mt++)
#pragma unroll
        for (int nt = 0; nt < 4; nt++)
#pragma unroll
            for (int q = 0; q < 4; q++) acc[mt][nt][q] = 0.f;

    LOAD_STAGE(0);
    LOAD_STAGE(1);
    LOAD_STAGE(2);

    for (int c = 0; c < C; c++) {
        cp_wait<2>();              // chunk c landed
        __syncthreads();           // all warps past chunk c-1 reads; data visible
        if (c + 3 < C) LOAD_STAGE(c + 3);
        else cp_commit();          // keep group indices aligned

        int s = c % NSTAGE;
        const uint32_t* Au = reinterpret_cast<const uint32_t*>(Abuf + s * A_FLOATS);
        const uint32_t* Bu = reinterpret_cast<const uint32_t*>(Bbuf + s * B_FLOATS);

#pragma unroll
        for (int ks = 0; ks < 4; ks++) {
            uint32_t af[4][4];
#pragma unroll
            for (int mt = 0; mt < 4; mt++) {
                int r = wm * 64 + mt * 16 + g;
                int base = r * ASTR + ks * 8 + tig;
                af[mt][0] = Au[base];
                af[mt][1] = Au[base + 8 * ASTR];
                af[mt][2] = Au[base + 4];
                af[mt][3] = Au[base + 8 * ASTR + 4];
            }
            uint32_t bf[4][2];
#pragma unroll
            for (int nt = 0; nt < 4; nt++) {
                int base = (ks * 8 + tig) * BSTR + wn * 32 + nt * 8 + g;
                // fused tf32 rounding of raw fp32 weights
                bf[nt][0] = f2tf32(__uint_as_float(Bu[base]));
                bf[nt][1] = f2tf32(__uint_as_float(Bu[base + 4 * BSTR]));
            }
#pragma unroll
            for (int mt = 0; mt < 4; mt++)
#pragma unroll
                for (int nt = 0; nt < 4; nt++)
                    mma_tf32(acc[mt][nt][0], acc[mt][nt][1], acc[mt][nt][2], acc[mt][nt][3],
                             af[mt][0], af[mt][1], af[mt][2], af[mt][3],
                             bf[nt][0], bf[nt][1]);
        }
    }

    // epilogue
    const float* bias = bias_all + (size_t)e * NT + n0;
#pragma unroll
    for (int mt = 0; mt < 4; mt++) {
        int r0 = m0 + wm * 64 + mt * 16 + g;
#pragma unroll
        for (int half = 0; half < 2; half++) {
            int r = r0 + half * 8;
            if (r >= mfill) continue;
            float* orow;
            float pm = 1.0f;
            if (MODE == 1) {
                orow = g_h + (size_t)(e * CAP + r) * H_FF + n0;
            } else {
                int tok = g_slot2tok[e * CAP + r];
                pm = g_pmax[tok];
                orow = out + (size_t)tok * D_MODEL + n0;
            }
#pragma unroll
            for (int nt = 0; nt < 4; nt++) {
                int col = wn * 32 + nt * 8 + 2 * tig;
                float v0 = acc[mt][nt][half * 2 + 0] + bias[col];
                float v1 = acc[mt][nt][half * 2 + 1] + bias[col + 1];
                float2 o;
                if (MODE == 1) {
                    o.x = f2tf32f(gelu_exact(v0));
                    o.y = f2tf32f(gelu_exact(v1));
                } else {
                    o.x = v0 * pm;
                    o.y = v1 * pm;
                }
                *reinterpret_cast<float2*>(orow + col) = o;
            }
        }
    }
#undef LOAD_STAGE
}

// ---------------- dropped tokens ----------------
__global__ void dropped_kernel(float* __restrict__ out)
{
    int tok = blockIdx.x;
    if (g_keep[tok]) return;
    float pm = g_pmax[tok];
    const float* tr = g_t + (size_t)tok * D_MODEL;
    float* orow = out + (size_t)tok * D_MODEL;
    for (int c = threadIdx.x; c < D_MODEL; c += 256) orow[c] = tr[c] * pm;
}

// ---------------- extras ----------------
__global__ void extras_kernel(float* __restrict__ out, int out_size)
{
    int i = blockIdx.x * 256 + threadIdx.x;
    if (i >= OUT_EXTRAS_N) return;
    long long off = (long long)OUT_COUNTS + i;
    if (off >= (long long)out_size) return;
    float v;
    if (i < 4)       v = g_counts[i];
    else if (i < 8)  v = g_probsum[i - 4];
    else if (i == 8) v = g_ndrop[0];
    else             v = g_pmax[i - 9];
    out[off] = v;
}

// ---------------- launch ----------------
extern "C" void kernel_launch(void* const* d_in, const int* in_sizes, int n_in,
                              void* d_out, int out_size)
{
    const float* x     = (const float*)d_in[0];
    const float* ln_g  = (const float*)d_in[1];
    const float* ln_b  = (const float*)d_in[2];
    const float* pre_W = (const float*)d_in[3];
    const float* pre_b = (const float*)d_in[4];
    const float* sw_W  = (const float*)d_in[5];
    const float* sw_b  = (const float*)d_in[6];
    const float* W1    = (const float*)d_in[7];
    const float* b1    = (const float*)d_in[8];
    const float* W2    = (const float*)d_in[9];
    const float* b2    = (const float*)d_in[10];
    float* out = (float*)d_out;

    cudaFuncSetAttribute(moe_mma<1>, cudaFuncAttributeMaxDynamicSharedMemorySize, SMEM_MOE);
    cudaFuncSetAttribute(moe_mma<2>, cudaFuncAttributeMaxDynamicSharedMemorySize, SMEM_MOE);

    ln_kernel<<<T_TOK, 256>>>(x, ln_g, ln_b);                                   // 0
    pre_gemm<<<dim3(D_MODEL / 128, T_TOK / 128), 256>>>(pre_W, pre_b);          // 1
    router_kernel<<<T_TOK, 256>>>(sw_W, sw_b);                                  // 2
    scan_kernel<<<1, 256>>>();                                                  // 3
    dispatch_kernel<<<ECAP, 128>>>();                                           // 4
    moe_mma<1><<<dim3(CAP / BM, H_FF / BN, NEXP), 256, SMEM_MOE>>>(W1, b1, nullptr);   // 5
    moe_mma<2><<<dim3(CAP / BM, D_MODEL / BN, NEXP), 256, SMEM_MOE>>>(W2, b2, out);    // 6
    probsum_kernel<<<NEXP, 256>>>();                                            // 7
    dropped_kernel<<<T_TOK, 256>>>(out);                                        // 8
    extras_kernel<<<(OUT_EXTRAS_N + 255) / 256, 256>>>(out, out_size);          // 9
}

// round 8
// speedup vs baseline: 4.9210x; 1.6219x over previous
#include <cuda_runtime.h>
#include <cuda_fp16.h>
#include <math.h>
#include <stdint.h>

// ---------------- problem dims (fixed) ----------------
#define BATCH   16
#define SEQ     576
#define T_TOK   9216
#define D_IN    1024
#define D_MODEL 2048
#define NEXP    4
#define H_FF    8192
#define CAP     3456
#define ECAP    (NEXP*CAP)      // 13824

#define OUT_COUNTS  (T_TOK*D_MODEL)
#define OUT_EXTRAS_N 9225

// ---------------- scratch ----------------
__device__ float  g_xn[(size_t)T_TOK * D_IN];
__device__ float  g_t [(size_t)T_TOK * D_MODEL];
__device__ float  g_probs[(size_t)T_TOK * NEXP];
__device__ float  g_pmax [T_TOK];
__device__ int    g_routes[T_TOK];
__device__ int    g_keep  [T_TOK];
__device__ int    g_slot2tok[ECAP];
__device__ int    g_Mfill[NEXP];
__device__ float  g_counts[NEXP];
__device__ float  g_probsum[NEXP];
__device__ float  g_ndrop[1];
__device__ __half g_ebh[(size_t)ECAP * D_MODEL];           // 56 MB  gathered tokens fp16
__device__ __half g_hh [(size_t)ECAP * H_FF];              // 226 MB hidden fp16
__device__ __half g_W1h[(size_t)NEXP * D_MODEL * H_FF];    // 134 MB
__device__ __half g_W2h[(size_t)NEXP * H_FF * D_MODEL];    // 134 MB

__device__ __forceinline__ float gelu_exact(float x) {
    return 0.5f * x * (1.0f + erff(x * 0.70710678118654752f));
}
__device__ __forceinline__ uint32_t h2_u32(__half2 h) {
    return *reinterpret_cast<uint32_t*>(&h);
}
__device__ __forceinline__ uint32_t smem_u32(const void* p) {
    uint32_t a;
    asm("{ .reg .u64 t; cvta.to.shared.u64 t, %1; cvt.u32.u64 %0, t; }" : "=r"(a) : "l"(p));
    return a;
}
__device__ __forceinline__ void cp16(uint32_t dst, const void* src) {
    asm volatile("cp.async.cg.shared.global [%0], [%1], 16;" :: "r"(dst), "l"(src) : "memory");
}
__device__ __forceinline__ void cp_commit() { asm volatile("cp.async.commit_group;" ::: "memory"); }
template<int N> __device__ __forceinline__ void cp_wait() {
    asm volatile("cp.async.wait_group %0;" :: "n"(N) : "memory");
}
__device__ __forceinline__ void ldsm4(uint32_t& r0, uint32_t& r1, uint32_t& r2, uint32_t& r3,
                                      uint32_t addr) {
    asm volatile("ldmatrix.sync.aligned.m8n8.x4.shared.b16 {%0,%1,%2,%3}, [%4];"
                 : "=r"(r0), "=r"(r1), "=r"(r2), "=r"(r3) : "r"(addr));
}
__device__ __forceinline__ void ldsm4t(uint32_t& r0, uint32_t& r1, uint32_t& r2, uint32_t& r3,
                                       uint32_t addr) {
    asm volatile("ldmatrix.sync.aligned.m8n8.x4.trans.shared.b16 {%0,%1,%2,%3}, [%4];"
                 : "=r"(r0), "=r"(r1), "=r"(r2), "=r"(r3) : "r"(addr));
}
__device__ __forceinline__ void mma_f16(float& c0, float& c1, float& c2, float& c3,
                                        uint32_t a0, uint32_t a1, uint32_t a2, uint32_t a3,
                                        uint32_t b0, uint32_t b1) {
    asm volatile(
        "mma.sync.aligned.m16n8k16.row.col.f32.f16.f16.f32 "
        "{%0,%1,%2,%3}, {%4,%5,%6,%7}, {%8,%9}, {%0,%1,%2,%3};"
        : "+f"(c0), "+f"(c1), "+f"(c2), "+f"(c3)
        : "r"(a0), "r"(a1), "r"(a2), "r"(a3), "r"(b0), "r"(b1));
}

// ---------------- LayerNorm ----------------
__global__ void ln_kernel(const float* __restrict__ x,
                          const float* __restrict__ g,
                          const float* __restrict__ b)
{
    int tok = blockIdx.x, tid = threadIdx.x;
    const float* xr = x + (size_t)tok * D_IN;
    __shared__ float red[256];
    float s = 0.f;
    for (int i = tid; i < D_IN; i += 256) s += xr[i];
    red[tid] = s; __syncthreads();
    for (int o = 128; o > 0; o >>= 1) { if (tid < o) red[tid] += red[tid + o]; __syncthreads(); }
    float mu = red[0] * (1.0f / D_IN);
    __syncthreads();
    float v = 0.f;
    for (int i = tid; i < D_IN; i += 256) { float d = xr[i] - mu; v += d * d; }
    red[tid] = v; __syncthreads();
    for (int o = 128; o > 0; o >>= 1) { if (tid < o) red[tid] += red[tid + o]; __syncthreads(); }
    float rstd = rsqrtf(red[0] * (1.0f / D_IN) + 1e-5f);
    float* xo = g_xn + (size_t)tok * D_IN;
    for (int i = tid; i < D_IN; i += 256)
        xo[i] = (xr[i] - mu) * rstd * g[i] + b[i];
}

// ---------------- pre-linear GEMM (fp32 FFMA, exact — feeds router argmax) ----------------
__global__ void pre_gemm(const float* __restrict__ W, const float* __restrict__ bias)
{
    const int K = D_IN, N = D_MODEL;
    int m0 = blockIdx.y * 128, n0 = blockIdx.x * 128, tid = threadIdx.x;
    __shared__ float As[8][128];
    __shared__ float Bs[8][128];
    int aRow = tid >> 1, aCol = (tid & 1) * 4;
    int bRow = tid >> 5, bCol = (tid & 31) * 4;
    int ty = tid >> 4, tx = tid & 15;
    const float* aPtr = g_xn + (size_t)(m0 + aRow) * K + aCol;
    float acc[8][8];
#pragma unroll
    for (int i = 0; i < 8; i++)
#pragma unroll
        for (int j = 0; j < 8; j++) acc[i][j] = 0.f;
    for (int k0 = 0; k0 < K; k0 += 8) {
        float4 av = *reinterpret_cast<const float4*>(aPtr + k0);
        float4 bv = *reinterpret_cast<const float4*>(&W[(size_t)(k0 + bRow) * N + n0 + bCol]);
        As[aCol + 0][aRow] = av.x; As[aCol + 1][aRow] = av.y;
        As[aCol + 2][aRow] = av.z; As[aCol + 3][aRow] = av.w;
        *reinterpret_cast<float4*>(&Bs[bRow][bCol]) = bv;
        __syncthreads();
#pragma unroll
        for (int k = 0; k < 8; k++) {
            float ra[8], rb[8];
#pragma unroll
            for (int i = 0; i < 8; i++) ra[i] = As[k][ty * 8 + i];
#pragma unroll
            for (int j = 0; j < 8; j++) rb[j] = Bs[k][tx * 8 + j];
#pragma unroll
            for (int i = 0; i < 8; i++)
#pragma unroll
                for (int j = 0; j < 8; j++) acc[i][j] += ra[i] * rb[j];
        }
        __syncthreads();
    }
#pragma unroll
    for (int i = 0; i < 8; i++) {
        int r = m0 + ty * 8 + i;
        float* orow = g_t + (size_t)r * N + n0;
#pragma unroll
        for (int j = 0; j < 8; j++) {
            float v = acc[i][j] + bias[n0 + tx * 8 + j];
            orow[tx * 8 + j] = gelu_exact(v);
        }
    }
}

// ---------------- router ----------------
__global__ void router_kernel(const float* __restrict__ swW, const float* __restrict__ swb)
{
    int tok = blockIdx.x, tid = threadIdx.x;
    const float* tr = g_t + (size_t)tok * D_MODEL;
    float a0 = 0.f, a1 = 0.f, a2 = 0.f, a3 = 0.f;
    for (int k = tid; k < D_MODEL; k += 256) {
        float tv = tr[k];
        const float* w = swW + (size_t)k * NEXP;
        a0 += tv * w[0]; a1 += tv * w[1]; a2 += tv * w[2]; a3 += tv * w[3];
    }
    __shared__ float red[4][256];
    red[0][tid] = a0; red[1][tid] = a1; red[2][tid] = a2; red[3][tid] = a3;
    __syncthreads();
    for (int o = 128; o > 0; o >>= 1) {
        if (tid < o) {
            red[0][tid] += red[0][tid + o]; red[1][tid] += red[1][tid + o];
            red[2][tid] += red[2][tid + o]; red[3][tid] += red[3][tid + o];
        }
        __syncthreads();
    }
    if (tid == 0) {
        float l[NEXP]; float mx = -1e30f; int arg = 0;
        for (int e = 0; e < NEXP; e++) {
            l[e] = red[e][0] + swb[e];
            if (l[e] > mx) { mx = l[e]; arg = e; }
        }
        float s = 0.f, p[NEXP];
        for (int e = 0; e < NEXP; e++) { p[e] = expf(l[e] - mx); s += p[e]; }
        float inv = 1.0f / s;
        for (int e = 0; e < NEXP; e++) g_probs[(size_t)tok * NEXP + e] = p[e] * inv;
        g_routes[tok] = arg;
        g_pmax[tok] = inv;
    }
}

__global__ void probsum_kernel()
{
    int e = blockIdx.x, tid = threadIdx.x;
    float s = 0.f;
    for (int t = tid; t < T_TOK; t += 256) s += g_probs[(size_t)t * NEXP + e];
    __shared__ float red[256];
    red[tid] = s; __syncthreads();
    for (int o = 128; o > 0; o >>= 1) { if (tid < o) red[tid] += red[tid + o]; __syncthreads(); }
    if (tid == 0) g_probsum[e] = red[0];
}

// ---------------- capacity scan ----------------
__global__ void scan_kernel()
{
    __shared__ int cnt[256][NEXP];
    int tid = threadIdx.x;
    const int CHUNK = T_TOK / 256;
    int base = tid * CHUNK;
    int c[NEXP] = {0, 0, 0, 0};
    for (int i = 0; i < CHUNK; i++) c[g_routes[base + i]]++;
    for (int e = 0; e < NEXP; e++) cnt[tid][e] = c[e];
    __syncthreads();
    if (tid == 0) {
        int run[NEXP] = {0, 0, 0, 0};
        for (int th = 0; th < 256; th++)
            for (int e = 0; e < NEXP; e++) {
                int tmp = cnt[th][e]; cnt[th][e] = run[e]; run[e] += tmp;
            }
        int nd = 0;
        for (int e = 0; e < NEXP; e++) {
            g_counts[e] = (float)run[e];
            int mf = run[e] < CAP ? run[e] : CAP;
            g_Mfill[e] = mf;
            nd += run[e] - mf;
        }
        g_ndrop[0] = (float)nd;
    }
    __syncthreads();
    int off[NEXP];
    for (int e = 0; e < NEXP; e++) off[e] = cnt[tid][e];
    for (int i = 0; i < CHUNK; i++) {
        int tok = base + i;
        int e = g_routes[tok];
        int p = off[e]++;
        int keep = (p < CAP) ? 1 : 0;
        g_keep[tok] = keep;
        if (keep) g_slot2tok[e * CAP + p] = tok;
    }
}

// ---------------- dispatch gather: g_ebh[slot] = fp16(g_t[tok]) ----------------
__global__ void dispatch_kernel()
{
    int slot = blockIdx.x;
    int e = slot / CAP, p = slot % CAP;
    if (p >= g_Mfill[e]) return;
    int tok = g_slot2tok[slot];
    uint2* dst = reinterpret_cast<uint2*>(g_ebh + (size_t)slot * D_MODEL);
    const float4* src = reinterpret_cast<const float4*>(g_t + (size_t)tok * D_MODEL);
    for (int i = threadIdx.x; i < D_MODEL / 4; i += 128) {
        float4 v = src[i];
        __half2 lo = __floats2half2_rn(v.x, v.y);
        __half2 hi = __floats2half2_rn(v.z, v.w);
        dst[i] = make_uint2(h2_u32(lo), h2_u32(hi));
    }
}

// ---------------- weight convert fp32 -> fp16 ----------------
__global__ void convert_w(const float* __restrict__ in, __half* __restrict__ out, size_t n4)
{
    size_t i = (size_t)blockIdx.x * blockDim.x + threadIdx.x;
    size_t stride = (size_t)gridDim.x * blockDim.x;
    const float4* I = reinterpret_cast<const float4*>(in);
    uint2* O = reinterpret_cast<uint2*>(out);
    for (; i < n4; i += stride) {
        float4 v = I[i];
        __half2 lo = __floats2half2_rn(v.x, v.y);
        __half2 hi = __floats2half2_rn(v.z, v.w);
        O[i] = make_uint2(h2_u32(lo), h2_u32(hi));
    }
}

// ---------------- fp16 mma expert GEMMs ----------------
// CTA tile 128x128x32, 8 warps (2m x 4n), warp tile 64x32, m16n8k16 MMAs.
// A smem: 128 rows x 64B (swizzle chunk^((row>>1)&3)); B smem: 32 rows x 256B (chunk^(row&7)).
#define BM 128
#define BN 128
#define BK 32
#define A_BYTES (BM * 64)        // 8192
#define B_BYTES (BK * 256)       // 8192
#define NSTAGE 4
#define SMEM_MOE (NSTAGE * (A_BYTES + B_BYTES))   // 65536

// MODE 1: g_hh[slot] = fp16(gelu(g_ebh[slot] @ W1h[e] + b1))   K=2048, NT=8192
// MODE 2: out[tok]   = (g_hh[slot] @ W2h[e] + b2) * pmax        K=8192, NT=2048
template<int MODE>
__global__ void __launch_bounds__(256, 1)
moe_mma(const __half* __restrict__ Wh, const float* __restrict__ bias_all,
        float* __restrict__ out)
{
    const int K  = (MODE == 1) ? D_MODEL : H_FF;
    const int NT = (MODE == 1) ? H_FF : D_MODEL;
    const int C  = K / BK;

    int e = blockIdx.z;
    int mfill = g_Mfill[e];
    int m0 = blockIdx.x * BM;
    if (m0 >= mfill) return;
    int n0 = blockIdx.y * BN;

    extern __shared__ char smem[];
    uint32_t sA = smem_u32(smem);
    uint32_t sB = sA + NSTAGE * A_BYTES;

    int tid = threadIdx.x;
    int w = tid >> 5, lane = tid & 31;
    int wm = w >> 2, wn = w & 3;
    int g = lane >> 2, tig = lane & 3;
    int l15 = lane & 15, hi = lane >> 4;

    const __half* Abase = ((MODE == 1) ? g_ebh : g_hh) + (size_t)(e * CAP + m0) * K;
    const __half* Bbase = Wh + (size_t)e * K * NT;

    // cp.async slots: A 2/thread, B 2/thread (16B each)
    const __half* a_src[2]; uint32_t a_dst[2];
#pragma unroll
    for (int i = 0; i < 2; i++) {
        int idx = i * 256 + tid;            // 0..511
        int row = idx >> 2, kc = idx & 3;   // 4 chunks per 64B row
        a_src[i] = Abase + (size_t)row * K + kc * 8;
        a_dst[i] = (uint32_t)(row * 64 + ((kc ^ ((row >> 1) & 3)) * 16));
    }
    const __half* b_src[2]; uint32_t b_dst[2];
#pragma unroll
    for (int i = 0; i < 2; i++) {
        int idx = i * 256 + tid;
        int row = idx >> 4, nc = idx & 15;  // 16 chunks per 256B row
        b_src[i] = Bbase + (size_t)row * NT + n0 + nc * 8;
        b_dst[i] = (uint32_t)(row * 256 + ((nc ^ (row & 7)) * 16));
    }

    // ldmatrix per-thread offsets (stage-relative)
    uint32_t offA[4][2];
#pragma unroll
    for (int mt = 0; mt < 4; mt++) {
        int row = wm * 64 + mt * 16 + l15;
        int xr = (row >> 1) & 3;
#pragma unroll
        for (int ks = 0; ks < 2; ks++)
            offA[mt][ks] = (uint32_t)(row * 64 + (((ks * 2 + hi) ^ xr) * 16));
    }
    uint32_t offB[2][2];
#pragma unroll
    for (int ks = 0; ks < 2; ks++) {
        int row = ks * 16 + l15;
#pragma unroll
        for (int p = 0; p < 2; p++) {
            int chunk = wn * 4 + p * 2 + hi;
            offB[ks][p] = (uint32_t)(row * 256 + ((chunk ^ (row & 7)) * 16));
        }
    }

#define LOAD_STAGE(c) do {                                                        \
        int s_ = (c) & (NSTAGE - 1);                                              \
        uint32_t aS = sA + (uint32_t)(s_ * A_BYTES);                              \
        uint32_t bS = sB + (uint32_t)(s_ * B_BYTES);                              \
        cp16(aS + a_dst[0], a_src[0] + (c) * BK);                                 \
        cp16(aS + a_dst[1], a_src[1] + (c) * BK);                                 \
        cp16(bS + b_dst[0], b_src[0] + (size_t)(c) * BK * NT);                    \
        cp16(bS + b_dst[1], b_src[1] + (size_t)(c) * BK * NT);                    \
        cp_commit();                                                              \
    } while (0)

    float acc[4][4][4];
#pragma unroll
    for (int mt = 0; mt < 4; mt++)
#pragma unroll
        for (int nt = 0; nt < 4; nt++)
#pragma unroll
            for (int q = 0; q < 4; q++) acc[mt][nt][q] = 0.f;

    LOAD_STAGE(0);
    LOAD_STAGE(1);
    LOAD_STAGE(2);

    for (int c = 0; c < C; c++) {
        cp_wait<2>();
        __syncthreads();
        if (c + 3 < C) LOAD_STAGE(c + 3);
        else cp_commit();

        int s = c & (NSTAGE - 1);
        uint32_t aS = sA + (uint32_t)(s * A_BYTES);
        uint32_t bS = sB + (uint32_t)(s * B_BYTES);

#pragma unroll
        for (int ks = 0; ks < 2; ks++) {
            uint32_t a[4][4];
#pragma unroll
            for (int mt = 0; mt < 4; mt++)
                ldsm4(a[mt][0], a[mt][1], a[mt][2], a[mt][3], aS + offA[mt][ks]);
            uint32_t b[2][4];
#pragma unroll
            for (int p = 0; p < 2; p++)
                ldsm4t(b[p][0], b[p][1], b[p][2], b[p][3], bS + offB[ks][p]);
#pragma unroll
            for (int mt = 0; mt < 4; mt++)
#pragma unroll
                for (int nt = 0; nt < 4; nt++) {
                    int p = nt >> 1, q = (nt & 1) * 2;
                    mma_f16(acc[mt][nt][0], acc[mt][nt][1], acc[mt][nt][2], acc[mt][nt][3],
                            a[mt][0], a[mt][1], a[mt][2], a[mt][3],
                            b[p][q], b[p][q + 1]);
                }
        }
    }

    // epilogue
    const float* bias = bias_all + (size_t)e * NT + n0;
#pragma unroll
    for (int mt = 0; mt < 4; mt++) {
        int r0 = m0 + wm * 64 + mt * 16 + g;
#pragma unroll
        for (int half = 0; half < 2; half++) {
            int r = r0 + half * 8;
            if (r >= mfill) continue;
#pragma unroll
            for (int nt = 0; nt < 4; nt++) {
                int col = wn * 32 + nt * 8 + 2 * tig;
                float v0 = acc[mt][nt][half * 2 + 0] + bias[col];
                float v1 = acc[mt][nt][half * 2 + 1] + bias[col + 1];
                if (MODE == 1) {
                    __half2 h2 = __floats2half2_rn(gelu_exact(v0), gelu_exact(v1));
                    *reinterpret_cast<uint32_t*>(
                        g_hh + (size_t)(e * CAP + r) * H_FF + n0 + col) = h2_u32(h2);
                } else {
                    int tok = g_slot2tok[e * CAP + r];
                    float pm = g_pmax[tok];
                    float2 o = make_float2(v0 * pm, v1 * pm);
                    *reinterpret_cast<float2*>(out + (size_t)tok * D_MODEL + n0 + col) = o;
                }
            }
        }
    }
#undef LOAD_STAGE
}

// ---------------- dropped tokens ----------------
__global__ void dropped_kernel(float* __restrict__ out)
{
    int tok = blockIdx.x;
    if (g_keep[tok]) return;
    float pm = g_pmax[tok];
    const float* tr = g_t + (size_t)tok * D_MODEL;
    float* orow = out + (size_t)tok * D_MODEL;
    for (int c = threadIdx.x; c < D_MODEL; c += 256) orow[c] = tr[c] * pm;
}

// ---------------- extras ----------------
__global__ void extras_kernel(float* __restrict__ out, int out_size)
{
    int i = blockIdx.x * 256 + threadIdx.x;
    if (i >= OUT_EXTRAS_N) return;
    long long off = (long long)OUT_COUNTS + i;
    if (off >= (long long)out_size) return;
    float v;
    if (i < 4)       v = g_counts[i];
    else if (i < 8)  v = g_probsum[i - 4];
    else if (i == 8) v = g_ndrop[0];
    else             v = g_pmax[i - 9];
    out[off] = v;
}

// ---------------- launch ----------------
extern "C" void kernel_launch(void* const* d_in, const int* in_sizes, int n_in,
                              void* d_out, int out_size)
{
    const float* x     = (const float*)d_in[0];
    const float* ln_g  = (const float*)d_in[1];
    const float* ln_b  = (const float*)d_in[2];
    const float* pre_W = (const float*)d_in[3];
    const float* pre_b = (const float*)d_in[4];
    const float* sw_W  = (const float*)d_in[5];
    const float* sw_b  = (const float*)d_in[6];
    const float* W1    = (const float*)d_in[7];
    const float* b1    = (const float*)d_in[8];
    const float* W2    = (const float*)d_in[9];
    const float* b2    = (const float*)d_in[10];
    float* out = (float*)d_out;

    __half *d_W1h = nullptr, *d_W2h = nullptr;
    cudaGetSymbolAddress((void**)&d_W1h, g_W1h);
    cudaGetSymbolAddress((void**)&d_W2h, g_W2h);
    cudaFuncSetAttribute(moe_mma<1>, cudaFuncAttributeMaxDynamicSharedMemorySize, SMEM_MOE);
    cudaFuncSetAttribute(moe_mma<2>, cudaFuncAttributeMaxDynamicSharedMemorySize, SMEM_MOE);

    const size_t WN4 = (size_t)NEXP * D_MODEL * H_FF / 4;

    ln_kernel<<<T_TOK, 256>>>(x, ln_g, ln_b);
    pre_gemm<<<dim3(D_MODEL / 128, T_TOK / 128), 256>>>(pre_W, pre_b);
    router_kernel<<<T_TOK, 256>>>(sw_W, sw_b);
    scan_kernel<<<1, 256>>>();
    dispatch_kernel<<<ECAP, 128>>>();
    convert_w<<<2048, 256>>>(W1, d_W1h, WN4);
    convert_w<<<2048, 256>>>(W2, d_W2h, WN4);
    moe_mma<1><<<dim3(CAP / BM, H_FF / BN, NEXP), 256, SMEM_MOE>>>(d_W1h, b1, nullptr);
    moe_mma<2><<<dim3(CAP / BM, D_MODEL / BN, NEXP), 256, SMEM_MOE>>>(d_W2h, b2, out);
    probsum_kernel<<<NEXP, 256>>>();
    dropped_kernel<<<T_TOK, 256>>>(out);
    extras_kernel<<<(OUT_EXTRAS_N + 255) / 256, 256>>>(out, out_size);
}

// round 9
// speedup vs baseline: 6.0105x; 1.2214x over previous
#include <cuda_runtime.h>
#include <cuda_fp16.h>
#include <math.h>
#include <stdint.h>

// ---------------- problem dims (fixed) ----------------
#define BATCH   16
#define SEQ     576
#define T_TOK   9216
#define D_IN    1024
#define D_MODEL 2048
#define NEXP    4
#define H_FF    8192
#define CAP     3456
#define ECAP    (NEXP*CAP)      // 13824

#define OUT_COUNTS  (T_TOK*D_MODEL)
#define OUT_EXTRAS_N 9225

// ---------------- scratch ----------------
__device__ float  g_t [(size_t)T_TOK * D_MODEL];
__device__ float  g_probs[(size_t)T_TOK * NEXP];
__device__ float  g_pmax [T_TOK];
__device__ int    g_routes[T_TOK];
__device__ int    g_keep  [T_TOK];
__device__ int    g_slot2tok[ECAP];
__device__ int    g_Mfill[NEXP];
__device__ float  g_counts[NEXP];
__device__ float  g_probsum[NEXP];
__device__ float  g_ndrop[1];
__device__ __half g_xh[(size_t)T_TOK * D_IN];              // 19 MB  ln out hi
__device__ __half g_xl[(size_t)T_TOK * D_IN];              // 19 MB  ln out lo
__device__ __half g_Wph[(size_t)D_IN * D_MODEL];           // 4 MB
__device__ __half g_Wpl[(size_t)D_IN * D_MODEL];           // 4 MB
__device__ __half g_ebh[(size_t)ECAP * D_MODEL];           // 56 MB  gathered tokens fp16
__device__ __half g_hh [(size_t)ECAP * H_FF];              // 226 MB hidden fp16
__device__ __half g_W1h[(size_t)NEXP * D_MODEL * H_FF];    // 134 MB
__device__ __half g_W2h[(size_t)NEXP * H_FF * D_MODEL];    // 134 MB

__device__ __forceinline__ float gelu_exact(float x) {
    return 0.5f * x * (1.0f + erff(x * 0.70710678118654752f));
}
__device__ __forceinline__ uint32_t h2_u32(__half2 h) {
    return *reinterpret_cast<uint32_t*>(&h);
}
__device__ __forceinline__ uint32_t smem_u32(const void* p) {
    uint32_t a;
    asm("{ .reg .u64 t; cvta.to.shared.u64 t, %1; cvt.u32.u64 %0, t; }" : "=r"(a) : "l"(p));
    return a;
}
__device__ __forceinline__ void cp16(uint32_t dst, const void* src) {
    asm volatile("cp.async.cg.shared.global [%0], [%1], 16;" :: "r"(dst), "l"(src) : "memory");
}
__device__ __forceinline__ void cp_commit() { asm volatile("cp.async.commit_group;" ::: "memory"); }
template<int N> __device__ __forceinline__ void cp_wait() {
    asm volatile("cp.async.wait_group %0;" :: "n"(N) : "memory");
}
__device__ __forceinline__ void ldsm4(uint32_t& r0, uint32_t& r1, uint32_t& r2, uint32_t& r3,
                                      uint32_t addr) {
    asm volatile("ldmatrix.sync.aligned.m8n8.x4.shared.b16 {%0,%1,%2,%3}, [%4];"
                 : "=r"(r0), "=r"(r1), "=r"(r2), "=r"(r3) : "r"(addr));
}
__device__ __forceinline__ void ldsm4t(uint32_t& r0, uint32_t& r1, uint32_t& r2, uint32_t& r3,
                                       uint32_t addr) {
    asm volatile("ldmatrix.sync.aligned.m8n8.x4.trans.shared.b16 {%0,%1,%2,%3}, [%4];"
                 : "=r"(r0), "=r"(r1), "=r"(r2), "=r"(r3) : "r"(addr));
}
__device__ __forceinline__ void mma_f16(float& c0, float& c1, float& c2, float& c3,
                                        uint32_t a0, uint32_t a1, uint32_t a2, uint32_t a3,
                                        uint32_t b0, uint32_t b1) {
    asm volatile(
        "mma.sync.aligned.m16n8k16.row.col.f32.f16.f16.f32 "
        "{%0,%1,%2,%3}, {%4,%5,%6,%7}, {%8,%9}, {%0,%1,%2,%3};"
        : "+f"(c0), "+f"(c1), "+f"(c2), "+f"(c3)
        : "r"(a0), "r"(a1), "r"(a2), "r"(a3), "r"(b0), "r"(b1));
}

// ---------------- LayerNorm -> split fp16 hi/lo ----------------
__global__ void ln_kernel(const float* __restrict__ x,
                          const float* __restrict__ g,
                          const float* __restrict__ b)
{
    int tok = blockIdx.x, tid = threadIdx.x;
    const float* xr = x + (size_t)tok * D_IN;
    __shared__ float red[256];
    float s = 0.f;
    for (int i = tid; i < D_IN; i += 256) s += xr[i];
    red[tid] = s; __syncthreads();
    for (int o = 128; o > 0; o >>= 1) { if (tid < o) red[tid] += red[tid + o]; __syncthreads(); }
    float mu = red[0] * (1.0f / D_IN);
    __syncthreads();
    float v = 0.f;
    for (int i = tid; i < D_IN; i += 256) { float d = xr[i] - mu; v += d * d; }
    red[tid] = v; __syncthreads();
    for (int o = 128; o > 0; o >>= 1) { if (tid < o) red[tid] += red[tid + o]; __syncthreads(); }
    float rstd = rsqrtf(red[0] * (1.0f / D_IN) + 1e-5f);
    __half* oh = g_xh + (size_t)tok * D_IN;
    __half* ol = g_xl + (size_t)tok * D_IN;
    for (int i = tid; i < D_IN; i += 256) {
        float xv = (xr[i] - mu) * rstd * g[i] + b[i];
        __half h = __float2half_rn(xv);
        oh[i] = h;
        ol[i] = __float2half_rn(xv - __half2float(h));
    }
}

// ---------------- weight split fp32 -> fp16 hi/lo ----------------
__global__ void split_w(const float* __restrict__ in, __half* __restrict__ oh,
                        __half* __restrict__ ol, size_t n)
{
    size_t i = (size_t)blockIdx.x * blockDim.x + threadIdx.x;
    size_t stride = (size_t)gridDim.x * blockDim.x;
    for (; i < n; i += stride) {
        float v = in[i];
        __half h = __float2half_rn(v);
        oh[i] = h;
        ol[i] = __float2half_rn(v - __half2float(h));
    }
}

// ---------------- weight convert fp32 -> fp16 ----------------
__global__ void convert_w(const float* __restrict__ in, __half* __restrict__ out, size_t n4)
{
    size_t i = (size_t)blockIdx.x * blockDim.x + threadIdx.x;
    size_t stride = (size_t)gridDim.x * blockDim.x;
    const float4* I = reinterpret_cast<const float4*>(in);
    uint2* O = reinterpret_cast<uint2*>(out);
    for (; i < n4; i += stride) {
        float4 v = I[i];
        __half2 lo = __floats2half2_rn(v.x, v.y);
        __half2 hi = __floats2half2_rn(v.z, v.w);
        O[i] = make_uint2(h2_u32(lo), h2_u32(hi));
    }
}

// ---------------- split-fp16 pre-GEMM: g_t = gelu(xn @ pre_W + b), ~fp32 precision ----
// acc = xh*Wh + xh*Wl + xl*Wh  (fp32 accum). M=9216, NT=2048, K=1024.
#define PBM 128
#define PBN 128
#define PBK 32
#define P_AB (PBM * 64)          // 8 KB per A operand per stage
#define P_BB (PBK * 256)         // 8 KB per B operand per stage
#define PSTAGE 3
#define SMEM_PRE (PSTAGE * 2 * (P_AB + P_BB))   // 98304

__global__ void __launch_bounds__(256, 1)
pre_mma(const float* __restrict__ bias)
{
    const int K = D_IN, NT = D_MODEL, C = K / PBK;

    int m0 = blockIdx.x * PBM;
    int n0 = blockIdx.y * PBN;

    extern __shared__ char smem[];
    uint32_t sAh = smem_u32(smem);
    uint32_t sAl = sAh + PSTAGE * P_AB;
    uint32_t sBh = sAl + PSTAGE * P_AB;
    uint32_t sBl = sBh + PSTAGE * P_BB;

    int tid = threadIdx.x;
    int w = tid >> 5, lane = tid & 31;
    int wm = w >> 2, wn = w & 3;
    int g = lane >> 2, tig = lane & 3;
    int l15 = lane & 15, hi = lane >> 4;

    const __half* Ah = g_xh + (size_t)m0 * K;
    const __half* Al = g_xl + (size_t)m0 * K;

    const __half* ah_src[2]; const __half* al_src[2]; uint32_t a_dst[2];
#pragma unroll
    for (int i = 0; i < 2; i++) {
        int idx = i * 256 + tid;
        int row = idx >> 2, kc = idx & 3;
        ah_src[i] = Ah + (size_t)row * K + kc * 8;
        al_src[i] = Al + (size_t)row * K + kc * 8;
        a_dst[i] = (uint32_t)(row * 64 + ((kc ^ ((row >> 1) & 3)) * 16));
    }
    const __half* bh_src[2]; const __half* bl_src[2]; uint32_t b_dst[2];
#pragma unroll
    for (int i = 0; i < 2; i++) {
        int idx = i * 256 + tid;
        int row = idx >> 4, nc = idx & 15;
        bh_src[i] = g_Wph + (size_t)row * NT + n0 + nc * 8;
        bl_src[i] = g_Wpl + (size_t)row * NT + n0 + nc * 8;
        b_dst[i] = (uint32_t)(row * 256 + ((nc ^ (row & 7)) * 16));
    }

    uint32_t offA[4][2];
#pragma unroll
    for (int mt = 0; mt < 4; mt++) {
        int row = wm * 64 + mt * 16 + l15;
        int xr = (row >> 1) & 3;
#pragma unroll
        for (int ks = 0; ks < 2; ks++)
            offA[mt][ks] = (uint32_t)(row * 64 + (((ks * 2 + hi) ^ xr) * 16));
    }
    uint32_t offB[2][2];
#pragma unroll
    for (int ks = 0; ks < 2; ks++) {
        int row = ks * 16 + l15;
#pragma unroll
        for (int p = 0; p < 2; p++) {
            int chunk = wn * 4 + p * 2 + hi;
            offB[ks][p] = (uint32_t)(row * 256 + ((chunk ^ (row & 7)) * 16));
        }
    }

#define PLOAD(c) do {                                                             \
        int s_ = (c) % PSTAGE;                                                    \
        uint32_t ahS = sAh + (uint32_t)(s_ * P_AB);                               \
        uint32_t alS = sAl + (uint32_t)(s_ * P_AB);                               \
        uint32_t bhS = sBh + (uint32_t)(s_ * P_BB);                               \
        uint32_t blS = sBl + (uint32_t)(s_ * P_BB);                               \
        cp16(ahS + a_dst[0], ah_src[0] + (c) * PBK);                              \
        cp16(ahS + a_dst[1], ah_src[1] + (c) * PBK);                              \
        cp16(alS + a_dst[0], al_src[0] + (c) * PBK);                              \
        cp16(alS + a_dst[1], al_src[1] + (c) * PBK);                              \
        cp16(bhS + b_dst[0], bh_src[0] + (size_t)(c) * PBK * NT);                 \
        cp16(bhS + b_dst[1], bh_src[1] + (size_t)(c) * PBK * NT);                 \
        cp16(blS + b_dst[0], bl_src[0] + (size_t)(c) * PBK * NT);                 \
        cp16(blS + b_dst[1], bl_src[1] + (size_t)(c) * PBK * NT);                 \
        cp_commit();                                                              \
    } while (0)

    float acc[4][4][4];
#pragma unroll
    for (int mt = 0; mt < 4; mt++)
#pragma unroll
        for (int nt = 0; nt < 4; nt++)
#pragma unroll
            for (int q = 0; q < 4; q++) acc[mt][nt][q] = 0.f;

    PLOAD(0);
    PLOAD(1);

    for (int c = 0; c < C; c++) {
        cp_wait<1>();
        __syncthreads();
        if (c + 2 < C) PLOAD(c + 2);
        else cp_commit();

        int s = c % PSTAGE;
        uint32_t ahS = sAh + (uint32_t)(s * P_AB);
        uint32_t alS = sAl + (uint32_t)(s * P_AB);
        uint32_t bhS = sBh + (uint32_t)(s * P_BB);
        uint32_t blS = sBl + (uint32_t)(s * P_BB);

#pragma unroll
        for (int ks = 0; ks < 2; ks++) {
            uint32_t ah[4][4], al[4][4];
#pragma unroll
            for (int mt = 0; mt < 4; mt++) {
                ldsm4(ah[mt][0], ah[mt][1], ah[mt][2], ah[mt][3], ahS + offA[mt][ks]);
                ldsm4(al[mt][0], al[mt][1], al[mt][2], al[mt][3], alS + offA[mt][ks]);
            }
            uint32_t bh[2][4], bl[2][4];
#pragma unroll
            for (int p = 0; p < 2; p++) {
                ldsm4t(bh[p][0], bh[p][1], bh[p][2], bh[p][3], bhS + offB[ks][p]);
                ldsm4t(bl[p][0], bl[p][1], bl[p][2], bl[p][3], blS + offB[ks][p]);
            }
#pragma unroll
            for (int mt = 0; mt < 4; mt++)
#pragma unroll
                for (int nt = 0; nt < 4; nt++) {
                    int p = nt >> 1, q = (nt & 1) * 2;
                    mma_f16(acc[mt][nt][0], acc[mt][nt][1], acc[mt][nt][2], acc[mt][nt][3],
                            ah[mt][0], ah[mt][1], ah[mt][2], ah[mt][3],
                            bh[p][q], bh[p][q + 1]);
                    mma_f16(acc[mt][nt][0], acc[mt][nt][1], acc[mt][nt][2], acc[mt][nt][3],
                            ah[mt][0], ah[mt][1], ah[mt][2], ah[mt][3],
                            bl[p][q], bl[p][q + 1]);
                    mma_f16(acc[mt][nt][0], acc[mt][nt][1], acc[mt][nt][2], acc[mt][nt][3],
                            al[mt][0], al[mt][1], al[mt][2], al[mt][3],
                            bh[p][q], bh[p][q + 1]);
                }
        }
    }

    // epilogue: gelu(acc + bias) -> g_t fp32
#pragma unroll
    for (int mt = 0; mt < 4; mt++) {
        int r0 = m0 + wm * 64 + mt * 16 + g;
#pragma unroll
        for (int half = 0; half < 2; half++) {
            int r = r0 + half * 8;
            float* orow = g_t + (size_t)r * D_MODEL + n0;
#pragma unroll
            for (int nt = 0; nt < 4; nt++) {
                int col = wn * 32 + nt * 8 + 2 * tig;
                float v0 = acc[mt][nt][half * 2 + 0] + bias[n0 + col];
                float v1 = acc[mt][nt][half * 2 + 1] + bias[n0 + col + 1];
                float2 o = make_float2(gelu_exact(v0), gelu_exact(v1));
                *reinterpret_cast<float2*>(orow + col) = o;
            }
        }
    }
#undef PLOAD
}

// ---------------- router ----------------
__global__ void router_kernel(const float* __restrict__ swW, const float* __restrict__ swb)
{
    int tok = blockIdx.x, tid = threadIdx.x;
    const float* tr = g_t + (size_t)tok * D_MODEL;
    float a0 = 0.f, a1 = 0.f, a2 = 0.f, a3 = 0.f;
    for (int k = tid; k < D_MODEL; k += 256) {
        float tv = tr[k];
        const float* w = swW + (size_t)k * NEXP;
        a0 += tv * w[0]; a1 += tv * w[1]; a2 += tv * w[2]; a3 += tv * w[3];
    }
    __shared__ float red[4][256];
    red[0][tid] = a0; red[1][tid] = a1; red[2][tid] = a2; red[3][tid] = a3;
    __syncthreads();
    for (int o = 128; o > 0; o >>= 1) {
        if (tid < o) {
            red[0][tid] += red[0][tid + o]; red[1][tid] += red[1][tid + o];
            red[2][tid] += red[2][tid + o]; red[3][tid] += red[3][tid + o];
        }
        __syncthreads();
    }
    if (tid == 0) {
        float l[NEXP]; float mx = -1e30f; int arg = 0;
        for (int e = 0; e < NEXP; e++) {
            l[e] = red[e][0] + swb[e];
            if (l[e] > mx) { mx = l[e]; arg = e; }
        }
        float s = 0.f, p[NEXP];
        for (int e = 0; e < NEXP; e++) { p[e] = expf(l[e] - mx); s += p[e]; }
        float inv = 1.0f / s;
        for (int e = 0; e < NEXP; e++) g_probs[(size_t)tok * NEXP + e] = p[e] * inv;
        g_routes[tok] = arg;
        g_pmax[tok] = inv;
    }
}

__global__ void probsum_kernel()
{
    int e = blockIdx.x, tid = threadIdx.x;
    float s = 0.f;
    for (int t = tid; t < T_TOK; t += 256) s += g_probs[(size_t)t * NEXP + e];
    __shared__ float red[256];
    red[tid] = s; __syncthreads();
    for (int o = 128; o > 0; o >>= 1) { if (tid < o) red[tid] += red[tid + o]; __syncthreads(); }
    if (tid == 0) g_probsum[e] = red[0];
}

// ---------------- capacity scan ----------------
__global__ void scan_kernel()
{
    __shared__ int cnt[256][NEXP];
    int tid = threadIdx.x;
    const int CHUNK = T_TOK / 256;
    int base = tid * CHUNK;
    int c[NEXP] = {0, 0, 0, 0};
    for (int i = 0; i < CHUNK; i++) c[g_routes[base + i]]++;
    for (int e = 0; e < NEXP; e++) cnt[tid][e] = c[e];
    __syncthreads();
    if (tid == 0) {
        int run[NEXP] = {0, 0, 0, 0};
        for (int th = 0; th < 256; th++)
            for (int e = 0; e < NEXP; e++) {
                int tmp = cnt[th][e]; cnt[th][e] = run[e]; run[e] += tmp;
            }
        int nd = 0;
        for (int e = 0; e < NEXP; e++) {
            g_counts[e] = (float)run[e];
            int mf = run[e] < CAP ? run[e] : CAP;
            g_Mfill[e] = mf;
            nd += run[e] - mf;
        }
        g_ndrop[0] = (float)nd;
    }
    __syncthreads();
    int off[NEXP];
    for (int e = 0; e < NEXP; e++) off[e] = cnt[tid][e];
    for (int i = 0; i < CHUNK; i++) {
        int tok = base + i;
        int e = g_routes[tok];
        int p = off[e]++;
        int keep = (p < CAP) ? 1 : 0;
        g_keep[tok] = keep;
        if (keep) g_slot2tok[e * CAP + p] = tok;
    }
}

// ---------------- dispatch gather: g_ebh[slot] = fp16(g_t[tok]) ----------------
__global__ void dispatch_kernel()
{
    int slot = blockIdx.x;
    int e = slot / CAP, p = slot % CAP;
    if (p >= g_Mfill[e]) return;
    int tok = g_slot2tok[slot];
    uint2* dst = reinterpret_cast<uint2*>(g_ebh + (size_t)slot * D_MODEL);
    const float4* src = reinterpret_cast<const float4*>(g_t + (size_t)tok * D_MODEL);
    for (int i = threadIdx.x; i < D_MODEL / 4; i += 128) {
        float4 v = src[i];
        __half2 lo = __floats2half2_rn(v.x, v.y);
        __half2 hi = __floats2half2_rn(v.z, v.w);
        dst[i] = make_uint2(h2_u32(lo), h2_u32(hi));
    }
}

// ---------------- fp16 mma expert GEMMs ----------------
#define BM 128
#define BN 128
#define BK 32
#define A_BYTES (BM * 64)        // 8192
#define B_BYTES (BK * 256)       // 8192
#define NSTAGE 4
#define SMEM_MOE (NSTAGE * (A_BYTES + B_BYTES))   // 65536

// MODE 1: g_hh[slot] = fp16(gelu(g_ebh[slot] @ W1h[e] + b1))   K=2048, NT=8192
// MODE 2: out[tok]   = (g_hh[slot] @ W2h[e] + b2) * pmax        K=8192, NT=2048
template<int MODE>
__global__ void __launch_bounds__(256, 1)
moe_mma(const __half* __restrict__ Wh, const float* __restrict__ bias_all,
        float* __restrict__ out)
{
    const int K  = (MODE == 1) ? D_MODEL : H_FF;
    const int NT = (MODE == 1) ? H_FF : D_MODEL;
    const int C  = K / BK;

    int e = blockIdx.z;
    int mfill = g_Mfill[e];
    int m0 = blockIdx.x * BM;
    if (m0 >= mfill) return;
    int n0 = blockIdx.y * BN;

    extern __shared__ char smem[];
    uint32_t sA = smem_u32(smem);
    uint32_t sB = sA + NSTAGE * A_BYTES;

    int tid = threadIdx.x;
    int w = tid >> 5, lane = tid & 31;
    int wm = w >> 2, wn = w & 3;
    int g = lane >> 2, tig = lane & 3;
    int l15 = lane & 15, hi = lane >> 4;

    const __half* Abase = ((MODE == 1) ? g_ebh : g_hh) + (size_t)(e * CAP + m0) * K;
    const __half* Bbase = Wh + (size_t)e * K * NT;

    const __half* a_src[2]; uint32_t a_dst[2];
#pragma unroll
    for (int i = 0; i < 2; i++) {
        int idx = i * 256 + tid;
        int row = idx >> 2, kc = idx & 3;
        a_src[i] = Abase + (size_t)row * K + kc * 8;
        a_dst[i] = (uint32_t)(row * 64 + ((kc ^ ((row >> 1) & 3)) * 16));
    }
    const __half* b_src[2]; uint32_t b_dst[2];
#pragma unroll
    for (int i = 0; i < 2; i++) {
        int idx = i * 256 + tid;
        int row = idx >> 4, nc = idx & 15;
        b_src[i] = Bbase + (size_t)row * NT + n0 + nc * 8;
        b_dst[i] = (uint32_t)(row * 256 + ((nc ^ (row & 7)) * 16));
    }

    uint32_t offA[4][2];
#pragma unroll
    for (int mt = 0; mt < 4; mt++) {
        int row = wm * 64 + mt * 16 + l15;
        int xr = (row >> 1) & 3;
#pragma unroll
        for (int ks = 0; ks < 2; ks++)
            offA[mt][ks] = (uint32_t)(row * 64 + (((ks * 2 + hi) ^ xr) * 16));
    }
    uint32_t offB[2][2];
#pragma unroll
    for (int ks = 0; ks < 2; ks++) {
        int row = ks * 16 + l15;
#pragma unroll
        for (int p = 0; p < 2; p++) {
            int chunk = wn * 4 + p * 2 + hi;
            offB[ks][p] = (uint32_t)(row * 256 + ((chunk ^ (row & 7)) * 16));
        }
    }

#define LOAD_STAGE(c) do {                                                        \
        int s_ = (c) & (NSTAGE - 1);                                              \
        uint32_t aS = sA + (uint32_t)(s_ * A_BYTES);                              \
        uint32_t bS = sB + (uint32_t)(s_ * B_BYTES);                              \
        cp16(aS + a_dst[0], a_src[0] + (c) * BK);                                 \
        cp16(aS + a_dst[1], a_src[1] + (c) * BK);                                 \
        cp16(bS + b_dst[0], b_src[0] + (size_t)(c) * BK * NT);                    \
        cp16(bS + b_dst[1], b_src[1] + (size_t)(c) * BK * NT);                    \
        cp_commit();                                                              \
    } while (0)

    float acc[4][4][4];
#pragma unroll
    for (int mt = 0; mt < 4; mt++)
#pragma unroll
        for (int nt = 0; nt < 4; nt++)
#pragma unroll
            for (int q = 0; q < 4; q++) acc[mt][nt][q] = 0.f;

    LOAD_STAGE(0);
    LOAD_STAGE(1);
    LOAD_STAGE(2);

    for (int c = 0; c < C; c++) {
        cp_wait<2>();
        __syncthreads();
        if (c + 3 < C) LOAD_STAGE(c + 3);
        else cp_commit();

        int s = c & (NSTAGE - 1);
        uint32_t aS = sA + (uint32_t)(s * A_BYTES);
        uint32_t bS = sB + (uint32_t)(s * B_BYTES);

#pragma unroll
        for (int ks = 0; ks < 2; ks++) {
            uint32_t a[4][4];
#pragma unroll
            for (int mt = 0; mt < 4; mt++)
                ldsm4(a[mt][0], a[mt][1], a[mt][2], a[mt][3], aS + offA[mt][ks]);
            uint32_t b[2][4];
#pragma unroll
            for (int p = 0; p < 2; p++)
                ldsm4t(b[p][0], b[p][1], b[p][2], b[p][3], bS + offB[ks][p]);
#pragma unroll
            for (int mt = 0; mt < 4; mt++)
#pragma unroll
                for (int nt = 0; nt < 4; nt++) {
                    int p = nt >> 1, q = (nt & 1) * 2;
                    mma_f16(acc[mt][nt][0], acc[mt][nt][1], acc[mt][nt][2], acc[mt][nt][3],
                            a[mt][0], a[mt][1], a[mt][2], a[mt][3],
                            b[p][q], b[p][q + 1]);
                }
        }
    }

    // epilogue
    const float* bias = bias_all + (size_t)e * NT + n0;
#pragma unroll
    for (int mt = 0; mt < 4; mt++) {
        int r0 = m0 + wm * 64 + mt * 16 + g;
#pragma unroll
        for (int half = 0; half < 2; half++) {
            int r = r0 + half * 8;
            if (r >= mfill) continue;
#pragma unroll
            for (int nt = 0; nt < 4; nt++) {
                int col = wn * 32 + nt * 8 + 2 * tig;
                float v0 = acc[mt][nt][half * 2 + 0] + bias[col];
                float v1 = acc[mt][nt][half * 2 + 1] + bias[col + 1];
                if (MODE == 1) {
                    __half2 h2 = __floats2half2_rn(gelu_exact(v0), gelu_exact(v1));
                    *reinterpret_cast<uint32_t*>(
                        g_hh + (size_t)(e * CAP + r) * H_FF + n0 + col) = h2_u32(h2);
                } else {
                    int tok = g_slot2tok[e * CAP + r];
                    float pm = g_pmax[tok];
                    float2 o = make_float2(v0 * pm, v1 * pm);
                    *reinterpret_cast<float2*>(out + (size_t)tok * D_MODEL + n0 + col) = o;
                }
            }
        }
    }
#undef LOAD_STAGE
}

// ---------------- dropped tokens ----------------
__global__ void dropped_kernel(float* __restrict__ out)
{
    int tok = blockIdx.x;
    if (g_keep[tok]) return;
    float pm = g_pmax[tok];
    const float* tr = g_t + (size_t)tok * D_MODEL;
    float* orow = out + (size_t)tok * D_MODEL;
    for (int c = threadIdx.x; c < D_MODEL; c += 256) orow[c] = tr[c] * pm;
}

// ---------------- extras ----------------
__global__ void extras_kernel(float* __restrict__ out, int out_size)
{
    int i = blockIdx.x * 256 + threadIdx.x;
    if (i >= OUT_EXTRAS_N) return;
    long long off = (long long)OUT_COUNTS + i;
    if (off >= (long long)out_size) return;
    float v;
    if (i < 4)       v = g_counts[i];
    else if (i < 8)  v = g_probsum[i - 4];
    else if (i == 8) v = g_ndrop[0];
    else             v = g_pmax[i - 9];
    out[off] = v;
}

// ---------------- launch ----------------
extern "C" void kernel_launch(void* const* d_in, const int* in_sizes, int n_in,
                              void* d_out, int out_size)
{
    const float* x     = (const float*)d_in[0];
    const float* ln_g  = (const float*)d_in[1];
    const float* ln_b  = (const float*)d_in[2];
    const float* pre_W = (const float*)d_in[3];
    const float* pre_b = (const float*)d_in[4];
    const float* sw_W  = (const float*)d_in[5];
    const float* sw_b  = (const float*)d_in[6];
    const float* W1    = (const float*)d_in[7];
    const float* b1    = (const float*)d_in[8];
    const float* W2    = (const float*)d_in[9];
    const float* b2    = (const float*)d_in[10];
    float* out = (float*)d_out;

    __half *d_W1h, *d_W2h, *d_Wph, *d_Wpl;
    cudaGetSymbolAddress((void**)&d_W1h, g_W1h);
    cudaGetSymbolAddress((void**)&d_W2h, g_W2h);
    cudaGetSymbolAddress((void**)&d_Wph, g_Wph);
    cudaGetSymbolAddress((void**)&d_Wpl, g_Wpl);
    cudaFuncSetAttribute(moe_mma<1>, cudaFuncAttributeMaxDynamicSharedMemorySize, SMEM_MOE);
    cudaFuncSetAttribute(moe_mma<2>, cudaFuncAttributeMaxDynamicSharedMemorySize, SMEM_MOE);
    cudaFuncSetAttribute(pre_mma, cudaFuncAttributeMaxDynamicSharedMemorySize, SMEM_PRE);

    const size_t WN4 = (size_t)NEXP * D_MODEL * H_FF / 4;

    ln_kernel<<<T_TOK, 256>>>(x, ln_g, ln_b);
    split_w<<<256, 256>>>(pre_W, d_Wph, d_Wpl, (size_t)D_IN * D_MODEL);
    pre_mma<<<dim3(T_TOK / PBM, D_MODEL / PBN), 256, SMEM_PRE>>>(pre_b);
    router_kernel<<<T_TOK, 256>>>(sw_W, sw_b);
    scan_kernel<<<1, 256>>>();
    dispatch_kernel<<<ECAP, 128>>>();
    convert_w<<<2048, 256>>>(W1, d_W1h, WN4);
    convert_w<<<2048, 256>>>(W2, d_W2h, WN4);
    moe_mma<1><<<dim3(CAP / BM, H_FF / BN, NEXP), 256, SMEM_MOE>>>(d_W1h, b1, nullptr);
    moe_mma<2><<<dim3(CAP / BM, D_MODEL / BN, NEXP), 256, SMEM_MOE>>>(d_W2h, b2, out);
    probsum_kernel<<<NEXP, 256>>>();
    dropped_kernel<<<T_TOK, 256>>>(out);
    extras_kernel<<<(OUT_EXTRAS_N + 255) / 256, 256>>>(out, out_size);
}